// round 1
// baseline (speedup 1.0000x reference)
#include <cuda_runtime.h>
#include <cstdint>

#define BATCH 8
#define NPIX  3136
#define CDIM  256
#define IDIM  128
#define OUT0  (BATCH*NPIX*CDIM)   // 6,422,528 floats, then w [B,N,N]

// ---------------- scratch (__device__ globals; no allocation allowed) ------
static __device__ float g_theta[BATCH*NPIX*IDIM];
static __device__ float g_phi  [BATCH*NPIX*IDIM];
static __device__ float g_gval [BATCH*NPIX*IDIM];
static __device__ float g_oval [BATCH*NPIX*IDIM];

// ---------------- packed fp32x2 FMA (Blackwell) ----------------------------
#define FMA2(d,a,b) asm("fma.rn.f32x2 %0, %1, %2, %0;" : "+l"(d) : "l"(a), "l"(b))
#define PACK2(d,x)  asm("mov.b64 %0, {%1, %1};" : "=l"(d) : "f"(x))

// 128x128 tile, 256 threads, 8x8 micro-tile per thread, packed f32x2 accum.
__device__ __forceinline__ void mma_tile(const float (*As)[132], const float (*Bs)[132],
                                         int ty, int tx, unsigned long long acc[8][4])
{
#pragma unroll
    for (int k = 0; k < 16; ++k) {
        float4 a0 = *(const float4*)&As[k][ty*4];
        float4 a1 = *(const float4*)&As[k][64 + ty*4];
        unsigned long long b0 = *(const unsigned long long*)&Bs[k][tx*4];
        unsigned long long b1 = *(const unsigned long long*)&Bs[k][tx*4 + 2];
        unsigned long long b2 = *(const unsigned long long*)&Bs[k][64 + tx*4];
        unsigned long long b3 = *(const unsigned long long*)&Bs[k][64 + tx*4 + 2];
        float av[8] = {a0.x,a0.y,a0.z,a0.w,a1.x,a1.y,a1.z,a1.w};
#pragma unroll
        for (int i = 0; i < 8; ++i) {
            unsigned long long ap;
            PACK2(ap, av[i]);
            FMA2(acc[i][0], ap, b0);
            FMA2(acc[i][1], ap, b1);
            FMA2(acc[i][2], ap, b2);
            FMA2(acc[i][3], ap, b3);
        }
    }
}

// ============================================================================
// NN GEMM: C[M,N] = A[M,K] * B[K,N]   (row-major; lda=K, ldb=ldc=N)
// N is an exact multiple of 128 (covered by gridDim.x tiles); M guarded.
// Optional residual add (same layout as C). blockIdx.z = batch (strides).
// ============================================================================
__global__ void __launch_bounds__(256)
sgemm_nn(const float* __restrict__ A, const float* __restrict__ B, float* __restrict__ C,
         int M, int N, int K, long long sA, long long sB, long long sC,
         const float* __restrict__ resid)
{
    __shared__ float As[16][132];
    __shared__ float Bs[16][132];
    const int b = blockIdx.z;
    A += (long long)b * sA;  B += (long long)b * sB;  C += (long long)b * sC;
    const int m0 = blockIdx.y * 128;
    const int n0 = blockIdx.x * 128;
    const int t  = threadIdx.x;
    const int tx = t & 15, ty = t >> 4;

    unsigned long long acc[8][4];
#pragma unroll
    for (int i = 0; i < 8; ++i)
#pragma unroll
        for (int j = 0; j < 4; ++j) acc[i][j] = 0ull;

    float4 aReg[2], bReg[2];
    const int nk = K >> 4;

    // prologue load (k0 = 0)
#pragma unroll
    for (int s = 0; s < 2; ++s) {
        int id = t + s*256;
        int r = id >> 2, c4 = id & 3;
        int gr = m0 + r;
        aReg[s] = (gr < M) ? *(const float4*)(A + (long long)gr*K + c4*4)
                           : make_float4(0.f,0.f,0.f,0.f);
        int kr = id >> 5, c = id & 31;
        bReg[s] = *(const float4*)(B + (long long)kr*N + n0 + c*4);
    }

    for (int kc = 0; kc < nk; ++kc) {
#pragma unroll
        for (int s = 0; s < 2; ++s) {
            int id = t + s*256;
            int r = id >> 2, c4 = id & 3;
            As[c4*4+0][r] = aReg[s].x; As[c4*4+1][r] = aReg[s].y;
            As[c4*4+2][r] = aReg[s].z; As[c4*4+3][r] = aReg[s].w;
            int kr = id >> 5, c = id & 31;
            *(float4*)&Bs[kr][c*4] = bReg[s];
        }
        __syncthreads();
        if (kc + 1 < nk) {
            const int k0 = (kc + 1) * 16;
#pragma unroll
            for (int s = 0; s < 2; ++s) {
                int id = t + s*256;
                int r = id >> 2, c4 = id & 3;
                int gr = m0 + r;
                aReg[s] = (gr < M) ? *(const float4*)(A + (long long)gr*K + k0 + c4*4)
                                   : make_float4(0.f,0.f,0.f,0.f);
                int kr = id >> 5, c = id & 31;
                bReg[s] = *(const float4*)(B + (long long)(k0+kr)*N + n0 + c*4);
            }
        }
        mma_tile(As, Bs, ty, tx, acc);
        __syncthreads();
    }

#pragma unroll
    for (int i = 0; i < 8; ++i) {
        int r  = (i < 4) ? (ty*4 + i) : (64 + ty*4 + (i-4));
        int gr = m0 + r;
        if (gr >= M) continue;
        float* Cr = C + (long long)gr*N + n0;
        float2 p0 = *(float2*)&acc[i][0];
        float2 p1 = *(float2*)&acc[i][1];
        float2 p2 = *(float2*)&acc[i][2];
        float2 p3 = *(float2*)&acc[i][3];
        float4 v0 = make_float4(p0.x, p0.y, p1.x, p1.y);
        float4 v1 = make_float4(p2.x, p2.y, p3.x, p3.y);
        if (resid) {
            const float* Rr = resid + (long long)gr*N + n0;
            float4 r0 = *(const float4*)(Rr + tx*4);
            float4 r1 = *(const float4*)(Rr + 64 + tx*4);
            v0.x += r0.x; v0.y += r0.y; v0.z += r0.z; v0.w += r0.w;
            v1.x += r1.x; v1.y += r1.y; v1.z += r1.z; v1.w += r1.w;
        }
        *(float4*)(Cr + tx*4)      = v0;
        *(float4*)(Cr + 64 + tx*4) = v1;
    }
}

// ============================================================================
// NT GEMM: C[M,N] = A[M,K] * B[N,K]^T  (both K-major, lda=ldb=K, ldc=N)
// Used for logits f = theta @ phi^T. M,N guarded; K multiple of 16.
// ============================================================================
__global__ void __launch_bounds__(256)
sgemm_nt(const float* __restrict__ A, const float* __restrict__ B, float* __restrict__ C,
         int M, int N, int K, long long sA, long long sB, long long sC)
{
    __shared__ float As[16][132];
    __shared__ float Bs[16][132];
    const int b = blockIdx.z;
    A += (long long)b * sA;  B += (long long)b * sB;  C += (long long)b * sC;
    const int m0 = blockIdx.y * 128;
    const int n0 = blockIdx.x * 128;
    const int t  = threadIdx.x;
    const int tx = t & 15, ty = t >> 4;

    unsigned long long acc[8][4];
#pragma unroll
    for (int i = 0; i < 8; ++i)
#pragma unroll
        for (int j = 0; j < 4; ++j) acc[i][j] = 0ull;

    float4 aReg[2], bReg[2];
    const int nk = K >> 4;

#pragma unroll
    for (int s = 0; s < 2; ++s) {
        int id = t + s*256;
        int r = id >> 2, c4 = id & 3;
        int gr = m0 + r, gn = n0 + r;
        aReg[s] = (gr < M) ? *(const float4*)(A + (long long)gr*K + c4*4)
                           : make_float4(0.f,0.f,0.f,0.f);
        bReg[s] = (gn < N) ? *(const float4*)(B + (long long)gn*K + c4*4)
                           : make_float4(0.f,0.f,0.f,0.f);
    }

    for (int kc = 0; kc < nk; ++kc) {
#pragma unroll
        for (int s = 0; s < 2; ++s) {
            int id = t + s*256;
            int r = id >> 2, c4 = id & 3;
            As[c4*4+0][r] = aReg[s].x; As[c4*4+1][r] = aReg[s].y;
            As[c4*4+2][r] = aReg[s].z; As[c4*4+3][r] = aReg[s].w;
            Bs[c4*4+0][r] = bReg[s].x; Bs[c4*4+1][r] = bReg[s].y;
            Bs[c4*4+2][r] = bReg[s].z; Bs[c4*4+3][r] = bReg[s].w;
        }
        __syncthreads();
        if (kc + 1 < nk) {
            const int k0 = (kc + 1) * 16;
#pragma unroll
            for (int s = 0; s < 2; ++s) {
                int id = t + s*256;
                int r = id >> 2, c4 = id & 3;
                int gr = m0 + r, gn = n0 + r;
                aReg[s] = (gr < M) ? *(const float4*)(A + (long long)gr*K + k0 + c4*4)
                                   : make_float4(0.f,0.f,0.f,0.f);
                bReg[s] = (gn < N) ? *(const float4*)(B + (long long)gn*K + k0 + c4*4)
                                   : make_float4(0.f,0.f,0.f,0.f);
            }
        }
        mma_tile(As, Bs, ty, tx, acc);
        __syncthreads();
    }

    const bool c0ok = (n0 + tx*4)      < N;   // group 0 cols
    const bool c1ok = (n0 + 64 + tx*4) < N;   // group 1 cols (N % 4 == 0)
#pragma unroll
    for (int i = 0; i < 8; ++i) {
        int r  = (i < 4) ? (ty*4 + i) : (64 + ty*4 + (i-4));
        int gr = m0 + r;
        if (gr >= M) continue;
        float* Cr = C + (long long)gr*N + n0;
        float2 p0 = *(float2*)&acc[i][0];
        float2 p1 = *(float2*)&acc[i][1];
        float2 p2 = *(float2*)&acc[i][2];
        float2 p3 = *(float2*)&acc[i][3];
        if (c0ok) *(float4*)(Cr + tx*4)      = make_float4(p0.x, p0.y, p1.x, p1.y);
        if (c1ok) *(float4*)(Cr + 64 + tx*4) = make_float4(p2.x, p2.y, p3.x, p3.y);
    }
}

// ============================================================================
// Row softmax in place on w region: one block per row of NPIX floats.
// ============================================================================
__global__ void __launch_bounds__(256)
softmax_rows(float* __restrict__ W)
{
    __shared__ float4 buf4[NPIX/4];
    __shared__ float  red[8];
    float* p = W + (long long)blockIdx.x * NPIX;
    const int t = threadIdx.x;

    float m = -3.402823466e38f;
    for (int i = t; i < NPIX/4; i += 256) {
        float4 v = *(const float4*)(p + i*4);
        buf4[i] = v;
        m = fmaxf(m, fmaxf(fmaxf(v.x, v.y), fmaxf(v.z, v.w)));
    }
#pragma unroll
    for (int o = 16; o > 0; o >>= 1) m = fmaxf(m, __shfl_xor_sync(0xffffffffu, m, o));
    if ((t & 31) == 0) red[t >> 5] = m;
    __syncthreads();
    float bm = red[0];
#pragma unroll
    for (int wv = 1; wv < 8; ++wv) bm = fmaxf(bm, red[wv]);
    __syncthreads();   // red reuse

    float s = 0.f;
    for (int i = t; i < NPIX/4; i += 256) {
        float4 v = buf4[i];
        v.x = __expf(v.x - bm); v.y = __expf(v.y - bm);
        v.z = __expf(v.z - bm); v.w = __expf(v.w - bm);
        buf4[i] = v;
        s += (v.x + v.y) + (v.z + v.w);
    }
#pragma unroll
    for (int o = 16; o > 0; o >>= 1) s += __shfl_xor_sync(0xffffffffu, s, o);
    if ((t & 31) == 0) red[t >> 5] = s;
    __syncthreads();
    float bs = red[0];
#pragma unroll
    for (int wv = 1; wv < 8; ++wv) bs += red[wv];
    const float inv = 1.0f / bs;

    for (int i = t; i < NPIX/4; i += 256) {
        float4 v = buf4[i];
        v.x *= inv; v.y *= inv; v.z *= inv; v.w *= inv;
        *(float4*)(p + i*4) = v;
    }
}

// ============================================================================
extern "C" void kernel_launch(void* const* d_in, const int* in_sizes, int n_in,
                              void* d_out, int out_size)
{
    const float* x   = (const float*)d_in[0];
    const float* wth = (const float*)d_in[1];
    const float* wph = (const float*)d_in[2];
    const float* wgv = (const float*)d_in[3];
    const float* wo  = (const float*)d_in[4];
    float* out0 = (float*)d_out;
    float* W    = out0 + (long long)OUT0;   // softmax weights output region

    float *th, *ph, *gv, *ov;
    cudaGetSymbolAddress((void**)&th, g_theta);
    cudaGetSymbolAddress((void**)&ph, g_phi);
    cudaGetSymbolAddress((void**)&gv, g_gval);
    cudaGetSymbolAddress((void**)&ov, g_oval);

    dim3 blk(256);
    const long long sI  = (long long)NPIX * IDIM;
    const long long sW  = (long long)NPIX * NPIX;

    // 1) projections: theta/phi/g = x @ W_*   [25088,256]x[256,128]
    sgemm_nn<<<dim3(1, 196, 1), blk>>>(x, wth, th, BATCH*NPIX, IDIM, CDIM, 0, 0, 0, nullptr);
    sgemm_nn<<<dim3(1, 196, 1), blk>>>(x, wph, ph, BATCH*NPIX, IDIM, CDIM, 0, 0, 0, nullptr);
    sgemm_nn<<<dim3(1, 196, 1), blk>>>(x, wgv, gv, BATCH*NPIX, IDIM, CDIM, 0, 0, 0, nullptr);

    // 2) logits: f = theta @ phi^T per batch -> written straight into w output region
    sgemm_nt<<<dim3(25, 25, BATCH), blk>>>(th, ph, W, NPIX, NPIX, IDIM, sI, sI, sW);

    // 3) softmax rows in place (produces final w output)
    softmax_rows<<<BATCH*NPIX, 256>>>(W);

    // 4) o = w @ g per batch   [3136,3136]x[3136,128]
    sgemm_nn<<<dim3(1, 25, BATCH), blk>>>(W, gv, ov, NPIX, IDIM, NPIX, sW, sI, sI, nullptr);

    // 5) out = o @ w_o + x     [25088,128]x[128,256] + residual
    sgemm_nn<<<dim3(2, 196, 1), blk>>>(ov, wo, out0, BATCH*NPIX, CDIM, IDIM, 0, 0, 0, x);
}

// round 6
// speedup vs baseline: 1.0532x; 1.0532x over previous
#include <cuda_runtime.h>
#include <cuda_bf16.h>
#include <cstdint>

#define BATCH 8
#define NPIX  3136
#define CDIM  256
#define IDIM  128
#define KEXT  768           // 6 combos x 128
#define OUT0  (BATCH*NPIX*CDIM)

typedef __nv_bfloat16 bf16;

// ---------------- scratch (__device__ globals; no allocation allowed) ------
static __device__ __align__(16) float g_gval[BATCH*NPIX*IDIM];
static __device__ __align__(16) float g_oval[BATCH*NPIX*IDIM];
static __device__ __align__(16) bf16  g_thx[(size_t)BATCH*NPIX*KEXT];  // theta ext splits
static __device__ __align__(16) bf16  g_phx[(size_t)BATCH*NPIX*KEXT];  // phi   ext splits
static __device__ __align__(16) bf16  g_gt0[BATCH*IDIM*NPIX];          // g^T hi
static __device__ __align__(16) bf16  g_gt1[BATCH*IDIM*NPIX];          // g^T lo
static __device__ __align__(16) bf16  g_whi[(size_t)BATCH*NPIX*NPIX];  // softmax hi
static __device__ __align__(16) bf16  g_wlo[(size_t)BATCH*NPIX*NPIX];  // softmax lo

// ---------------- PTX helpers ----------------------------------------------
__device__ __forceinline__ uint32_t smem_u32(const void* p) {
    uint32_t a;
    asm("{ .reg .u64 t; cvta.to.shared.u64 t, %1; cvt.u32.u64 %0, t; }" : "=r"(a) : "l"(p));
    return a;
}
__device__ __forceinline__ void cp_async16(uint32_t dst, const void* src) {
    unsigned long long gsrc = __cvta_generic_to_global(const_cast<void*>(src));
    asm volatile("cp.async.cg.shared.global [%0], [%1], 16;" :: "r"(dst), "l"(gsrc) : "memory");
}
#define CP_COMMIT()        asm volatile("cp.async.commit_group;" ::: "memory")
#define CP_WAIT0()         asm volatile("cp.async.wait_group 0;" ::: "memory")

__device__ __forceinline__ void ldsm4(uint32_t& r0, uint32_t& r1, uint32_t& r2, uint32_t& r3,
                                      uint32_t addr) {
    asm volatile("ldmatrix.sync.aligned.m8n8.x4.shared.b16 {%0,%1,%2,%3}, [%4];"
                 : "=r"(r0), "=r"(r1), "=r"(r2), "=r"(r3) : "r"(addr));
}
__device__ __forceinline__ void mma_bf16(float* c, const uint32_t* a, const uint32_t* b) {
    asm volatile("mma.sync.aligned.m16n8k16.row.col.f32.bf16.bf16.f32 "
                 "{%0,%1,%2,%3}, {%4,%5,%6,%7}, {%8,%9}, {%0,%1,%2,%3};"
                 : "+f"(c[0]), "+f"(c[1]), "+f"(c[2]), "+f"(c[3])
                 : "r"(a[0]), "r"(a[1]), "r"(a[2]), "r"(a[3]), "r"(b[0]), "r"(b[1]));
}

// swizzle for 128B-row (SW128) or 64B-row (SW64) tiles
template<int ROWB>
__device__ __forceinline__ uint32_t swz(uint32_t off) {
    return (ROWB == 128) ? (off ^ ((off >> 3) & 0x70))
                         : (off ^ ((off >> 3) & 0x30));
}

// 128-row x (ROWB bytes) tile loader via cp.async, row clamp.
template<int ROWB>
__device__ __forceinline__ void load_tile(uint32_t sbase, const char* gsrc,
                                          long rowStride, int maxRow, int tid) {
    const int CPR = ROWB / 16;          // 16B chunks per row
    const int TOT = 128 * CPR;          // total chunks
#pragma unroll
    for (int i = 0; i < TOT/256; ++i) {
        int idx = tid + i*256;
        int r = idx / CPR, cq = idx % CPR;
        int rr = r < maxRow ? r : maxRow - 1;
        const char* src = gsrc + (long)rr*rowStride + cq*16;
        cp_async16(sbase + swz<ROWB>(r*ROWB + cq*16), src);
    }
}

// Per-warp fragment loads (A: 4 m16 tiles, B: 4 n8 tiles) for one k16 step.
template<int ROWB>
__device__ __forceinline__ void lds_afrag(uint32_t abase, int m_w, int ks, int lane,
                                          uint32_t Af[4][4]) {
    int q = lane >> 3;
#pragma unroll
    for (int i = 0; i < 4; ++i) {
        int row = m_w + i*16 + ((q & 1) << 3) + (lane & 7);
        int col = ks*32 + ((q >> 1) << 4);
        ldsm4(Af[i][0], Af[i][1], Af[i][2], Af[i][3], abase + swz<ROWB>(row*ROWB + col));
    }
}
template<int ROWB>
__device__ __forceinline__ void lds_bfrag(uint32_t bbase, int n_w, int ks, int lane,
                                          uint32_t Bf[4][2]) {
    int q = lane >> 3;
#pragma unroll
    for (int jj = 0; jj < 2; ++jj) {
        int row = n_w + jj*16 + ((q >> 1) << 3) + (lane & 7);
        int col = ks*32 + ((q & 1) << 4);
        ldsm4(Bf[jj*2][0], Bf[jj*2][1], Bf[jj*2+1][0], Bf[jj*2+1][1],
              bbase + swz<ROWB>(row*ROWB + col));
    }
}

// ============================================================================
// bf16 NT GEMM via mma.sync: C[M,N] = A[M,K]·B[N,K]^T, K mult of 64.
// Block 128x128, 8 warps (2x4), warp tile 64x32, static 32KB smem, 1 stage.
// ============================================================================
__global__ void __launch_bounds__(256)
gemm_nt_bf16(const bf16* __restrict__ A, const bf16* __restrict__ B, float* __restrict__ C,
             int M, int N, int Kext, long sA, long sB, long sC)
{
    __shared__ __align__(128) char smbuf[32768];
    const uint32_t sb = smem_u32(smbuf);
    const int tid = threadIdx.x, lane = tid & 31, wid = tid >> 5;
    const int m_w = (wid & 1)*64, n_w = (wid >> 1)*32;
    const int b = blockIdx.z, m0 = blockIdx.y*128, n0 = blockIdx.x*128;
    const char* Ab = (const char*)(A + (size_t)b*sA) + (size_t)m0*Kext*2;
    const char* Bb = (const char*)(B + (size_t)b*sB) + (size_t)n0*Kext*2;
    const long rsA = (long)Kext*2;
    const int  mRem = M - m0, nRem = N - n0;
    const int  nc = Kext >> 6;

    float acc[4][4][4];
#pragma unroll
    for (int i = 0; i < 4; ++i)
#pragma unroll
        for (int j = 0; j < 4; ++j)
#pragma unroll
            for (int v = 0; v < 4; ++v) acc[i][j][v] = 0.f;

    for (int c = 0; c < nc; ++c) {
        load_tile<128>(sb,         Ab + (long)c*128, rsA, mRem, tid);
        load_tile<128>(sb + 16384, Bb + (long)c*128, rsA, nRem, tid);
        CP_COMMIT();
        CP_WAIT0();
        __syncthreads();
        uint32_t Af[4][4], Bf[4][2];
#pragma unroll
        for (int ks = 0; ks < 4; ++ks) {
            lds_afrag<128>(sb,         m_w, ks, lane, Af);
            lds_bfrag<128>(sb + 16384, n_w, ks, lane, Bf);
#pragma unroll
            for (int i = 0; i < 4; ++i)
#pragma unroll
                for (int j = 0; j < 4; ++j)
                    mma_bf16(acc[i][j], Af[i], Bf[j]);
        }
        __syncthreads();
    }

    float* Cb = C + (size_t)b*sC;
    const int g = lane >> 2, tg = lane & 3;
#pragma unroll
    for (int i = 0; i < 4; ++i) {
        int r0 = m0 + m_w + i*16 + g;
        int r1 = r0 + 8;
#pragma unroll
        for (int j = 0; j < 4; ++j) {
            int col = n0 + n_w + j*8 + tg*2;
            if (col < N) {
                if (r0 < M) *(float2*)(Cb + (size_t)r0*N + col) = make_float2(acc[i][j][0], acc[i][j][1]);
                if (r1 < M) *(float2*)(Cb + (size_t)r1*N + col) = make_float2(acc[i][j][2], acc[i][j][3]);
            }
        }
    }
}

// ============================================================================
// o = w·g via mma.sync, 3 combos/chunk: whi·ghi + whi·glo + wlo·ghi.
// Block 128(m) x 128(n=i), K chunk 32 (64B-row tiles), static 32KB, 1 stage.
// grid (25, 8).
// ============================================================================
__global__ void __launch_bounds__(256)
ogemm_mma(const bf16* __restrict__ Whi, const bf16* __restrict__ Wlo,
          const bf16* __restrict__ Gh,  const bf16* __restrict__ Gl,
          float* __restrict__ Ov)
{
    __shared__ __align__(128) char smbuf[32768];
    const uint32_t sb = smem_u32(smbuf);
    const int tid = threadIdx.x, lane = tid & 31, wid = tid >> 5;
    const int m_w = (wid & 1)*64, n_w = (wid >> 1)*32;
    const int b = blockIdx.y, m0 = blockIdx.x*128;
    const long rsW = (long)NPIX*2;
    const char* Ah = (const char*)(Whi + ((size_t)b*NPIX + m0)*NPIX);
    const char* Al = (const char*)(Wlo + ((size_t)b*NPIX + m0)*NPIX);
    const char* Bh = (const char*)(Gh + (size_t)b*IDIM*NPIX);
    const char* Bl = (const char*)(Gl + (size_t)b*IDIM*NPIX);
    const int mRem = NPIX - m0;
    const int nc = NPIX / 32;   // 98

    float acc[4][4][4];
#pragma unroll
    for (int i = 0; i < 4; ++i)
#pragma unroll
        for (int j = 0; j < 4; ++j)
#pragma unroll
            for (int v = 0; v < 4; ++v) acc[i][j][v] = 0.f;

    for (int c = 0; c < nc; ++c) {
        const long kb = (long)c*64;   // 32 bf16 = 64 bytes along K
        load_tile<64>(sb,          Ah + kb, rsW, mRem, tid);   // whi  8KB
        load_tile<64>(sb +  8192,  Al + kb, rsW, mRem, tid);   // wlo
        load_tile<64>(sb + 16384,  Bh + kb, rsW, 128,  tid);   // ghi
        load_tile<64>(sb + 24576,  Bl + kb, rsW, 128,  tid);   // glo
        CP_COMMIT();
        CP_WAIT0();
        __syncthreads();
        uint32_t Af[4][4], Bg[4][2], Bl2[4][2];
#pragma unroll
        for (int ks = 0; ks < 2; ++ks) {
            lds_afrag<64>(sb,          m_w, ks, lane, Af);     // whi
            lds_bfrag<64>(sb + 16384,  n_w, ks, lane, Bg);     // ghi
            lds_bfrag<64>(sb + 24576,  n_w, ks, lane, Bl2);    // glo
#pragma unroll
            for (int i = 0; i < 4; ++i)
#pragma unroll
                for (int j = 0; j < 4; ++j) {
                    mma_bf16(acc[i][j], Af[i], Bg[j]);
                    mma_bf16(acc[i][j], Af[i], Bl2[j]);
                }
            lds_afrag<64>(sb + 8192, m_w, ks, lane, Af);       // wlo
#pragma unroll
            for (int i = 0; i < 4; ++i)
#pragma unroll
                for (int j = 0; j < 4; ++j)
                    mma_bf16(acc[i][j], Af[i], Bg[j]);
        }
        __syncthreads();
    }

    float* Ob = Ov + (size_t)b*NPIX*IDIM;
    const int g = lane >> 2, tg = lane & 3;
#pragma unroll
    for (int i = 0; i < 4; ++i) {
        int r0 = m0 + m_w + i*16 + g;
        int r1 = r0 + 8;
#pragma unroll
        for (int j = 0; j < 4; ++j) {
            int col = n_w + j*8 + tg*2;
            if (r0 < NPIX) *(float2*)(Ob + (size_t)r0*IDIM + col) = make_float2(acc[i][j][0], acc[i][j][1]);
            if (r1 < NPIX) *(float2*)(Ob + (size_t)r1*IDIM + col) = make_float2(acc[i][j][2], acc[i][j][3]);
        }
    }
}

// ---------------- packed fp32x2 FMA (small fp32 GEMMs) ---------------------
#define FMA2(d,a,b) asm("fma.rn.f32x2 %0, %1, %2, %0;" : "+l"(d) : "l"(a), "l"(b))
#define PACK2(d,x)  asm("mov.b64 %0, {%1, %1};" : "=l"(d) : "f"(x))

__device__ __forceinline__ void mma_tile(const float (*As)[132], const float (*Bs)[132],
                                         int ty, int tx, unsigned long long acc[8][4])
{
#pragma unroll
    for (int k = 0; k < 16; ++k) {
        float4 a0 = *(const float4*)&As[k][ty*4];
        float4 a1 = *(const float4*)&As[k][64 + ty*4];
        unsigned long long b0 = *(const unsigned long long*)&Bs[k][tx*4];
        unsigned long long b1 = *(const unsigned long long*)&Bs[k][tx*4 + 2];
        unsigned long long b2 = *(const unsigned long long*)&Bs[k][64 + tx*4];
        unsigned long long b3 = *(const unsigned long long*)&Bs[k][64 + tx*4 + 2];
        float av[8] = {a0.x,a0.y,a0.z,a0.w,a1.x,a1.y,a1.z,a1.w};
#pragma unroll
        for (int i = 0; i < 8; ++i) {
            unsigned long long ap;
            PACK2(ap, av[i]);
            FMA2(acc[i][0], ap, b0);
            FMA2(acc[i][1], ap, b1);
            FMA2(acc[i][2], ap, b2);
            FMA2(acc[i][3], ap, b3);
        }
    }
}

// ============================================================================
// fp32 NN GEMM (g projection + final epilogue)
// ============================================================================
__global__ void __launch_bounds__(256)
sgemm_nn(const float* __restrict__ A, const float* __restrict__ B, float* __restrict__ C,
         int M, int N, int K, const float* __restrict__ resid)
{
    __shared__ float As[16][132];
    __shared__ float Bs[16][132];
    const int m0 = blockIdx.y * 128;
    const int n0 = blockIdx.x * 128;
    const int t  = threadIdx.x;
    const int tx = t & 15, ty = t >> 4;

    unsigned long long acc[8][4];
#pragma unroll
    for (int i = 0; i < 8; ++i)
#pragma unroll
        for (int j = 0; j < 4; ++j) acc[i][j] = 0ull;

    float4 aReg[2], bReg[2];
    const int nk = K >> 4;

#pragma unroll
    for (int s = 0; s < 2; ++s) {
        int id = t + s*256;
        int r = id >> 2, c4 = id & 3;
        int gr = m0 + r;
        aReg[s] = (gr < M) ? *(const float4*)(A + (long long)gr*K + c4*4)
                           : make_float4(0.f,0.f,0.f,0.f);
        int kr = id >> 5, c = id & 31;
        bReg[s] = *(const float4*)(B + (long long)kr*N + n0 + c*4);
    }

    for (int kc = 0; kc < nk; ++kc) {
#pragma unroll
        for (int s = 0; s < 2; ++s) {
            int id = t + s*256;
            int r = id >> 2, c4 = id & 3;
            As[c4*4+0][r] = aReg[s].x; As[c4*4+1][r] = aReg[s].y;
            As[c4*4+2][r] = aReg[s].z; As[c4*4+3][r] = aReg[s].w;
            int kr = id >> 5, c = id & 31;
            *(float4*)&Bs[kr][c*4] = bReg[s];
        }
        __syncthreads();
        if (kc + 1 < nk) {
            const int k0 = (kc + 1) * 16;
#pragma unroll
            for (int s = 0; s < 2; ++s) {
                int id = t + s*256;
                int r = id >> 2, c4 = id & 3;
                int gr = m0 + r;
                aReg[s] = (gr < M) ? *(const float4*)(A + (long long)gr*K + k0 + c4*4)
                                   : make_float4(0.f,0.f,0.f,0.f);
                int kr = id >> 5, c = id & 31;
                bReg[s] = *(const float4*)(B + (long long)(k0+kr)*N + n0 + c*4);
            }
        }
        mma_tile(As, Bs, ty, tx, acc);
        __syncthreads();
    }

#pragma unroll
    for (int i = 0; i < 8; ++i) {
        int r  = (i < 4) ? (ty*4 + i) : (64 + ty*4 + (i-4));
        int gr = m0 + r;
        if (gr >= M) continue;
        float* Cr = C + (long long)gr*N + n0;
        float2 p0 = *(float2*)&acc[i][0];
        float2 p1 = *(float2*)&acc[i][1];
        float2 p2 = *(float2*)&acc[i][2];
        float2 p3 = *(float2*)&acc[i][3];
        float4 v0 = make_float4(p0.x, p0.y, p1.x, p1.y);
        float4 v1 = make_float4(p2.x, p2.y, p3.x, p3.y);
        if (resid) {
            const float* Rr = resid + (long long)gr*N + n0;
            float4 r0 = *(const float4*)(Rr + tx*4);
            float4 r1 = *(const float4*)(Rr + 64 + tx*4);
            v0.x += r0.x; v0.y += r0.y; v0.z += r0.z; v0.w += r0.w;
            v1.x += r1.x; v1.y += r1.y; v1.z += r1.z; v1.w += r1.w;
        }
        *(float4*)(Cr + tx*4)      = v0;
        *(float4*)(Cr + 64 + tx*4) = v1;
    }
}

// ============================================================================
// Projection + 3-way split -> extended-K bf16 layout.
// blockIdx.z: 0 = theta (ext: h,h,m,m,h,l), 1 = phi (ext: h,m,h,m,l,h).
// ============================================================================
__device__ __forceinline__ void split3(float a, bf16& h, bf16& m, bf16& l) {
    h = __float2bfloat16(a); float r  = a - __bfloat162float(h);
    m = __float2bfloat16(r); float r2 = r - __bfloat162float(m);
    l = __float2bfloat16(r2);
}

__global__ void __launch_bounds__(256)
proj_split(const float* __restrict__ A,
           const float* __restrict__ Bth, const float* __restrict__ Bph,
           bf16* __restrict__ THX, bf16* __restrict__ PHX, int M, int K)
{
    const int N = IDIM;
    const float* B = blockIdx.z ? Bph : Bth;
    bf16* EXT = blockIdx.z ? PHX : THX;
    int ph0, ph1, ph2, pm0, pm1, pl0;
    if (blockIdx.z == 0) { ph0=0; ph1=128; ph2=512; pm0=256; pm1=384; pl0=640; }
    else                 { ph0=0; ph1=256; ph2=640; pm0=128; pm1=384; pl0=512; }

    __shared__ float As[16][132];
    __shared__ float Bs[16][132];
    const int m0 = blockIdx.y * 128;
    const int t  = threadIdx.x;
    const int tx = t & 15, ty = t >> 4;

    unsigned long long acc[8][4];
#pragma unroll
    for (int i = 0; i < 8; ++i)
#pragma unroll
        for (int j = 0; j < 4; ++j) acc[i][j] = 0ull;

    float4 aReg[2], bReg[2];
    const int nk = K >> 4;

#pragma unroll
    for (int s = 0; s < 2; ++s) {
        int id = t + s*256;
        int r = id >> 2, c4 = id & 3;
        int gr = m0 + r;
        aReg[s] = (gr < M) ? *(const float4*)(A + (long long)gr*K + c4*4)
                           : make_float4(0.f,0.f,0.f,0.f);
        int kr = id >> 5, c = id & 31;
        bReg[s] = *(const float4*)(B + (long long)kr*N + c*4);
    }

    for (int kc = 0; kc < nk; ++kc) {
#pragma unroll
        for (int s = 0; s < 2; ++s) {
            int id = t + s*256;
            int r = id >> 2, c4 = id & 3;
            As[c4*4+0][r] = aReg[s].x; As[c4*4+1][r] = aReg[s].y;
            As[c4*4+2][r] = aReg[s].z; As[c4*4+3][r] = aReg[s].w;
            int kr = id >> 5, c = id & 31;
            *(float4*)&Bs[kr][c*4] = bReg[s];
        }
        __syncthreads();
        if (kc + 1 < nk) {
            const int k0 = (kc + 1) * 16;
#pragma unroll
            for (int s = 0; s < 2; ++s) {
                int id = t + s*256;
                int r = id >> 2, c4 = id & 3;
                int gr = m0 + r;
                aReg[s] = (gr < M) ? *(const float4*)(A + (long long)gr*K + k0 + c4*4)
                                   : make_float4(0.f,0.f,0.f,0.f);
                int kr = id >> 5, c = id & 31;
                bReg[s] = *(const float4*)(B + (long long)(k0+kr)*N + c*4);
            }
        }
        mma_tile(As, Bs, ty, tx, acc);
        __syncthreads();
    }

#pragma unroll
    for (int i = 0; i < 8; ++i) {
        int r  = (i < 4) ? (ty*4 + i) : (64 + ty*4 + (i-4));
        int gr = m0 + r;
        if (gr >= M) continue;
        float2 p0 = *(float2*)&acc[i][0];
        float2 p1 = *(float2*)&acc[i][1];
        float2 p2 = *(float2*)&acc[i][2];
        float2 p3 = *(float2*)&acc[i][3];
        float vals[8] = {p0.x, p0.y, p1.x, p1.y, p2.x, p2.y, p3.x, p3.y};
        bf16* rowp = EXT + (size_t)gr*KEXT;
#pragma unroll
        for (int grp = 0; grp < 2; ++grp) {
            union { bf16 h[4]; uint2 u; } uh, um, ul;
#pragma unroll
            for (int j = 0; j < 4; ++j)
                split3(vals[grp*4 + j], uh.h[j], um.h[j], ul.h[j]);
            int col = grp*64 + tx*4;
            *(uint2*)(rowp + ph0 + col) = uh.u;
            *(uint2*)(rowp + ph1 + col) = uh.u;
            *(uint2*)(rowp + ph2 + col) = uh.u;
            *(uint2*)(rowp + pm0 + col) = um.u;
            *(uint2*)(rowp + pm1 + col) = um.u;
            *(uint2*)(rowp + pl0 + col) = ul.u;
        }
    }
}

// ============================================================================
// g transpose + 2-way bf16 split: g[B*N,I] -> gt0/gt1 [B][I][N]
// ============================================================================
__global__ void __launch_bounds__(256)
transpose_split(const float* __restrict__ g, bf16* __restrict__ t0, bf16* __restrict__ t1)
{
    __shared__ float tile[32][33];
    const int b = blockIdx.z, n0 = blockIdx.x*32, i0 = blockIdx.y*32;
    const int lane = threadIdx.x & 31, wrow = threadIdx.x >> 5;
#pragma unroll
    for (int rr = 0; rr < 4; ++rr) {
        int n = n0 + wrow + rr*8;
        tile[wrow + rr*8][lane] = g[((size_t)b*NPIX + n)*IDIM + i0 + lane];
    }
    __syncthreads();
#pragma unroll
    for (int rr = 0; rr < 4; ++rr) {
        int i = i0 + wrow + rr*8;
        int n = n0 + lane;
        float a = tile[lane][wrow + rr*8];
        bf16 h = __float2bfloat16(a);
        bf16 l = __float2bfloat16(a - __bfloat162float(h));
        size_t o = ((size_t)b*IDIM + i)*NPIX + n;
        t0[o] = h; t1[o] = l;
    }
}

// ============================================================================
// Row softmax in place; also emits bf16 hi/lo splits of w.
// ============================================================================
__global__ void __launch_bounds__(256)
softmax_rows(float* __restrict__ W, bf16* __restrict__ Whi, bf16* __restrict__ Wlo)
{
    __shared__ float4 buf4[NPIX/4];
    __shared__ float  red[8];
    const size_t row = blockIdx.x;
    float* p = W + row * NPIX;
    bf16* ph = Whi + row * NPIX;
    bf16* pl = Wlo + row * NPIX;
    const int t = threadIdx.x;

    float m = -3.402823466e38f;
    for (int i = t; i < NPIX/4; i += 256) {
        float4 v = *(const float4*)(p + i*4);
        buf4[i] = v;
        m = fmaxf(m, fmaxf(fmaxf(v.x, v.y), fmaxf(v.z, v.w)));
    }
#pragma unroll
    for (int o = 16; o > 0; o >>= 1) m = fmaxf(m, __shfl_xor_sync(0xffffffffu, m, o));
    if ((t & 31) == 0) red[t >> 5] = m;
    __syncthreads();
    float bm = red[0];
#pragma unroll
    for (int wv = 1; wv < 8; ++wv) bm = fmaxf(bm, red[wv]);
    __syncthreads();

    float s = 0.f;
    for (int i = t; i < NPIX/4; i += 256) {
        float4 v = buf4[i];
        v.x = __expf(v.x - bm); v.y = __expf(v.y - bm);
        v.z = __expf(v.z - bm); v.w = __expf(v.w - bm);
        buf4[i] = v;
        s += (v.x + v.y) + (v.z + v.w);
    }
#pragma unroll
    for (int o = 16; o > 0; o >>= 1) s += __shfl_xor_sync(0xffffffffu, s, o);
    if ((t & 31) == 0) red[t >> 5] = s;
    __syncthreads();
    float bs = red[0];
#pragma unroll
    for (int wv = 1; wv < 8; ++wv) bs += red[wv];
    const float inv = 1.0f / bs;

    for (int i = t; i < NPIX/4; i += 256) {
        float4 v = buf4[i];
        v.x *= inv; v.y *= inv; v.z *= inv; v.w *= inv;
        *(float4*)(p + i*4) = v;
        union { bf16 h[4]; uint2 u; } H, L;
        H.h[0] = __float2bfloat16(v.x); L.h[0] = __float2bfloat16(v.x - __bfloat162float(H.h[0]));
        H.h[1] = __float2bfloat16(v.y); L.h[1] = __float2bfloat16(v.y - __bfloat162float(H.h[1]));
        H.h[2] = __float2bfloat16(v.z); L.h[2] = __float2bfloat16(v.z - __bfloat162float(H.h[2]));
        H.h[3] = __float2bfloat16(v.w); L.h[3] = __float2bfloat16(v.w - __bfloat162float(H.h[3]));
        *(uint2*)(ph + i*4) = H.u;
        *(uint2*)(pl + i*4) = L.u;
    }
}

// ============================================================================
extern "C" void kernel_launch(void* const* d_in, const int* in_sizes, int n_in,
                              void* d_out, int out_size)
{
    const float* x   = (const float*)d_in[0];
    const float* wth = (const float*)d_in[1];
    const float* wph = (const float*)d_in[2];
    const float* wgv = (const float*)d_in[3];
    const float* wo  = (const float*)d_in[4];
    float* out0 = (float*)d_out;
    float* W    = out0 + (long long)OUT0;

    float *gv, *ov;
    bf16 *thx, *phx, *gt0, *gt1, *whi, *wlo;
    cudaGetSymbolAddress((void**)&gv,  g_gval);
    cudaGetSymbolAddress((void**)&ov,  g_oval);
    cudaGetSymbolAddress((void**)&thx, g_thx);
    cudaGetSymbolAddress((void**)&phx, g_phx);
    cudaGetSymbolAddress((void**)&gt0, g_gt0);
    cudaGetSymbolAddress((void**)&gt1, g_gt1);
    cudaGetSymbolAddress((void**)&whi, g_whi);
    cudaGetSymbolAddress((void**)&wlo, g_wlo);

    dim3 blk(256);

    // 1) theta+phi projections with ext-split epilogue; g projection fp32
    proj_split<<<dim3(1, 196, 2), blk>>>(x, wth, wph, thx, phx, BATCH*NPIX, CDIM);
    sgemm_nn<<<dim3(1, 196, 1), blk>>>(x, wgv, gv, BATCH*NPIX, IDIM, CDIM, nullptr);

    // 2) g transpose + 2-way split
    transpose_split<<<dim3(98, 4, 8), blk>>>(gv, gt0, gt1);

    // 3) logits = thx @ phx^T  (ext K=768, bf16 HMMA) -> w region
    gemm_nt_bf16<<<dim3(25, 25, 8), blk>>>(thx, phx, W, NPIX, NPIX, KEXT,
                                           (long)NPIX*KEXT, (long)NPIX*KEXT,
                                           (long)NPIX*NPIX);

    // 4) softmax rows in place + emit bf16 splits
    softmax_rows<<<BATCH*NPIX, 256>>>(W, whi, wlo);

    // 5) o = w @ g (bf16 HMMA, 3 combos)
    ogemm_mma<<<dim3(25, 8), blk>>>(whi, wlo, gt0, gt1, ov);

    // 6) out = o @ w_o + x
    sgemm_nn<<<dim3(2, 196, 1), blk>>>(ov, wo, out0, BATCH*NPIX, CDIM, IDIM, x);
}

// round 8
// speedup vs baseline: 1.3727x; 1.3034x over previous
#include <cuda_runtime.h>
#include <cuda_bf16.h>
#include <cstdint>

#define BATCH 8
#define NPIX  3136
#define CDIM  256
#define IDIM  128
#define KEXT  768           // 6 combos x 128
#define OUT0  (BATCH*NPIX*CDIM)

typedef __nv_bfloat16 bf16;

// ---------------- scratch (__device__ globals; no allocation allowed) ------
static __device__ __align__(16) float g_gval[BATCH*NPIX*IDIM];
static __device__ __align__(16) float g_oval[BATCH*NPIX*IDIM];
static __device__ __align__(16) bf16  g_thx[(size_t)BATCH*NPIX*KEXT];  // theta ext splits
static __device__ __align__(16) bf16  g_phx[(size_t)BATCH*NPIX*KEXT];  // phi   ext splits
static __device__ __align__(16) bf16  g_gt0[BATCH*IDIM*NPIX];          // g^T hi
static __device__ __align__(16) bf16  g_gt1[BATCH*IDIM*NPIX];          // g^T lo
static __device__ __align__(16) bf16  g_whi[(size_t)BATCH*NPIX*NPIX];  // softmax hi
static __device__ __align__(16) bf16  g_wlo[(size_t)BATCH*NPIX*NPIX];  // softmax lo

// ---------------- PTX helpers ----------------------------------------------
__device__ __forceinline__ uint32_t smem_u32(const void* p) {
    uint32_t a;
    asm("{ .reg .u64 t; cvta.to.shared.u64 t, %1; cvt.u32.u64 %0, t; }" : "=r"(a) : "l"(p));
    return a;
}
__device__ __forceinline__ void cp_async16(uint32_t dst, const void* src) {
    unsigned long long gsrc = __cvta_generic_to_global(const_cast<void*>(src));
    asm volatile("cp.async.cg.shared.global [%0], [%1], 16;" :: "r"(dst), "l"(gsrc) : "memory");
}
#define CP_COMMIT()        asm volatile("cp.async.commit_group;" ::: "memory")
#define CP_WAIT1()         asm volatile("cp.async.wait_group 1;" ::: "memory")
#define CP_WAIT0()         asm volatile("cp.async.wait_group 0;" ::: "memory")

__device__ __forceinline__ void ldsm4(uint32_t& r0, uint32_t& r1, uint32_t& r2, uint32_t& r3,
                                      uint32_t addr) {
    asm volatile("ldmatrix.sync.aligned.m8n8.x4.shared.b16 {%0,%1,%2,%3}, [%4];"
                 : "=r"(r0), "=r"(r1), "=r"(r2), "=r"(r3) : "r"(addr));
}
__device__ __forceinline__ void mma_bf16(float* c, const uint32_t* a, const uint32_t* b) {
    asm volatile("mma.sync.aligned.m16n8k16.row.col.f32.bf16.bf16.f32 "
                 "{%0,%1,%2,%3}, {%4,%5,%6,%7}, {%8,%9}, {%0,%1,%2,%3};"
                 : "+f"(c[0]), "+f"(c[1]), "+f"(c[2]), "+f"(c[3])
                 : "r"(a[0]), "r"(a[1]), "r"(a[2]), "r"(a[3]), "r"(b[0]), "r"(b[1]));
}

// swizzle for 128/64/32-byte row tiles
template<int ROWB>
__device__ __forceinline__ uint32_t swz(uint32_t off) {
    const uint32_t mask = (ROWB == 128) ? 0x70u : (ROWB == 64) ? 0x30u : 0x10u;
    return off ^ ((off >> 3) & mask);
}

// 128-row x (ROWB bytes) tile loader via cp.async, row clamp.
template<int ROWB>
__device__ __forceinline__ void load_tile(uint32_t sbase, const char* gsrc,
                                          long rowStride, int maxRow, int tid) {
    const int CPR = ROWB / 16;          // 16B chunks per row
    const int TOT = 128 * CPR;          // total chunks
#pragma unroll
    for (int i = 0; i < TOT/256; ++i) {
        int idx = tid + i*256;
        int r = idx / CPR, cq = idx % CPR;
        int rr = r < maxRow ? r : maxRow - 1;
        const char* src = gsrc + (long)rr*rowStride + cq*16;
        cp_async16(sbase + swz<ROWB>(r*ROWB + cq*16), src);
    }
}

// Per-warp fragment loads (A: 4 m16 tiles, B: 4 n8 tiles) for one k16 step.
template<int ROWB>
__device__ __forceinline__ void lds_afrag(uint32_t abase, int m_w, int ks, int lane,
                                          uint32_t Af[4][4]) {
    int q = lane >> 3;
#pragma unroll
    for (int i = 0; i < 4; ++i) {
        int row = m_w + i*16 + ((q & 1) << 3) + (lane & 7);
        int col = ks*32 + ((q >> 1) << 4);
        ldsm4(Af[i][0], Af[i][1], Af[i][2], Af[i][3], abase + swz<ROWB>(row*ROWB + col));
    }
}
template<int ROWB>
__device__ __forceinline__ void lds_bfrag(uint32_t bbase, int n_w, int ks, int lane,
                                          uint32_t Bf[4][2]) {
    int q = lane >> 3;
#pragma unroll
    for (int jj = 0; jj < 2; ++jj) {
        int row = n_w + jj*16 + ((q >> 1) << 3) + (lane & 7);
        int col = ks*32 + ((q & 1) << 4);
        ldsm4(Bf[jj*2][0], Bf[jj*2][1], Bf[jj*2+1][0], Bf[jj*2+1][1],
              bbase + swz<ROWB>(row*ROWB + col));
    }
}

// ============================================================================
// bf16 NT GEMM via mma.sync: C[M,N] = A[M,K]·B[N,K]^T, K mult of 32.
// Block 128x128, 8 warps, warp tile 64x32.
// 2-stage cp.async double buffer, K-chunk 32 (64B rows), 32KB static smem.
// ============================================================================
__global__ void __launch_bounds__(256)
gemm_nt_bf16(const bf16* __restrict__ A, const bf16* __restrict__ B, float* __restrict__ C,
             int M, int N, int Kext, long sA, long sB, long sC)
{
    __shared__ __align__(128) char smbuf[32768];   // 2 stages x (8KB A + 8KB B)
    const uint32_t sb = smem_u32(smbuf);
    const int tid = threadIdx.x, lane = tid & 31, wid = tid >> 5;
    const int m_w = (wid & 1)*64, n_w = (wid >> 1)*32;
    const int b = blockIdx.z, m0 = blockIdx.y*128, n0 = blockIdx.x*128;
    const char* Ab = (const char*)(A + (size_t)b*sA) + (size_t)m0*Kext*2;
    const char* Bb = (const char*)(B + (size_t)b*sB) + (size_t)n0*Kext*2;
    const long rsA = (long)Kext*2;
    const int  mRem = M - m0, nRem = N - n0;
    const int  nc = Kext >> 5;          // chunks of 32 (24 for KEXT)

    float acc[4][4][4];
#pragma unroll
    for (int i = 0; i < 4; ++i)
#pragma unroll
        for (int j = 0; j < 4; ++j)
#pragma unroll
            for (int v = 0; v < 4; ++v) acc[i][j][v] = 0.f;

    // stage s base = sb + s*16384; A at +0 (8KB), B at +8192
    load_tile<64>(sb,        Ab, rsA, mRem, tid);
    load_tile<64>(sb + 8192, Bb, rsA, nRem, tid);
    CP_COMMIT();

    for (int c = 0; c < nc; ++c) {
        if (c + 1 < nc) {
            uint32_t s1 = ((c + 1) & 1) * 16384u;
            load_tile<64>(sb + s1,        Ab + (long)(c+1)*64, rsA, mRem, tid);
            load_tile<64>(sb + s1 + 8192, Bb + (long)(c+1)*64, rsA, nRem, tid);
            CP_COMMIT();
            CP_WAIT1();
        } else {
            CP_WAIT0();
        }
        __syncthreads();
        uint32_t abase = sb + (uint32_t)(c & 1)*16384u;
        uint32_t bbase = abase + 8192;
        uint32_t Af[4][4], Bf[4][2];
#pragma unroll
        for (int ks = 0; ks < 2; ++ks) {
            lds_afrag<64>(abase, m_w, ks, lane, Af);
            lds_bfrag<64>(bbase, n_w, ks, lane, Bf);
#pragma unroll
            for (int i = 0; i < 4; ++i)
#pragma unroll
                for (int j = 0; j < 4; ++j)
                    mma_bf16(acc[i][j], Af[i], Bf[j]);
        }
        __syncthreads();
    }

    float* Cb = C + (size_t)b*sC;
    const int g = lane >> 2, tg = lane & 3;
#pragma unroll
    for (int i = 0; i < 4; ++i) {
        int r0 = m0 + m_w + i*16 + g;
        int r1 = r0 + 8;
#pragma unroll
        for (int j = 0; j < 4; ++j) {
            int col = n0 + n_w + j*8 + tg*2;
            if (col < N) {
                if (r0 < M) *(float2*)(Cb + (size_t)r0*N + col) = make_float2(acc[i][j][0], acc[i][j][1]);
                if (r1 < M) *(float2*)(Cb + (size_t)r1*N + col) = make_float2(acc[i][j][2], acc[i][j][3]);
            }
        }
    }
}

// ============================================================================
// o = w·g via mma.sync, 3 combos/chunk: whi·ghi + whi·glo + wlo·ghi.
// Block 128(m) x 128(n=i). 2-stage double buffer, K-chunk 16 (32B rows), 32KB.
// grid (25, 8).
// ============================================================================
__global__ void __launch_bounds__(256)
ogemm_mma(const bf16* __restrict__ Whi, const bf16* __restrict__ Wlo,
          const bf16* __restrict__ Gh,  const bf16* __restrict__ Gl,
          float* __restrict__ Ov)
{
    __shared__ __align__(128) char smbuf[32768];   // 2 stages x (4 tiles x 4KB)
    const uint32_t sb = smem_u32(smbuf);
    const int tid = threadIdx.x, lane = tid & 31, wid = tid >> 5;
    const int m_w = (wid & 1)*64, n_w = (wid >> 1)*32;
    const int b = blockIdx.y, m0 = blockIdx.x*128;
    const long rsW = (long)NPIX*2;
    const char* Ah = (const char*)(Whi + ((size_t)b*NPIX + m0)*NPIX);
    const char* Al = (const char*)(Wlo + ((size_t)b*NPIX + m0)*NPIX);
    const char* Bh = (const char*)(Gh + (size_t)b*IDIM*NPIX);
    const char* Bl = (const char*)(Gl + (size_t)b*IDIM*NPIX);
    const int mRem = NPIX - m0;
    const int nc = NPIX / 16;   // 196 chunks of K=16

    float acc[4][4][4];
#pragma unroll
    for (int i = 0; i < 4; ++i)
#pragma unroll
        for (int j = 0; j < 4; ++j)
#pragma unroll
            for (int v = 0; v < 4; ++v) acc[i][j][v] = 0.f;

    // stage layout (16KB): [whi 4KB][wlo 4KB][ghi 4KB][glo 4KB]
    {
        load_tile<32>(sb,         Ah, rsW, mRem, tid);
        load_tile<32>(sb +  4096, Al, rsW, mRem, tid);
        load_tile<32>(sb +  8192, Bh, rsW, 128,  tid);
        load_tile<32>(sb + 12288, Bl, rsW, 128,  tid);
        CP_COMMIT();
    }

    for (int c = 0; c < nc; ++c) {
        if (c + 1 < nc) {
            uint32_t s1 = sb + (uint32_t)((c + 1) & 1)*16384u;
            const long kb = (long)(c+1)*32;
            load_tile<32>(s1,         Ah + kb, rsW, mRem, tid);
            load_tile<32>(s1 +  4096, Al + kb, rsW, mRem, tid);
            load_tile<32>(s1 +  8192, Bh + kb, rsW, 128,  tid);
            load_tile<32>(s1 + 12288, Bl + kb, rsW, 128,  tid);
            CP_COMMIT();
            CP_WAIT1();
        } else {
            CP_WAIT0();
        }
        __syncthreads();
        uint32_t base = sb + (uint32_t)(c & 1)*16384u;
        uint32_t Af[4][4], Bg[4][2], Bl2[4][2];
        lds_afrag<32>(base,          m_w, 0, lane, Af);     // whi
        lds_bfrag<32>(base +  8192,  n_w, 0, lane, Bg);     // ghi
        lds_bfrag<32>(base + 12288,  n_w, 0, lane, Bl2);    // glo
#pragma unroll
        for (int i = 0; i < 4; ++i)
#pragma unroll
            for (int j = 0; j < 4; ++j) {
                mma_bf16(acc[i][j], Af[i], Bg[j]);
                mma_bf16(acc[i][j], Af[i], Bl2[j]);
            }
        lds_afrag<32>(base + 4096, m_w, 0, lane, Af);       // wlo
#pragma unroll
        for (int i = 0; i < 4; ++i)
#pragma unroll
            for (int j = 0; j < 4; ++j)
                mma_bf16(acc[i][j], Af[i], Bg[j]);
        __syncthreads();
    }

    float* Ob = Ov + (size_t)b*NPIX*IDIM;
    const int g = lane >> 2, tg = lane & 3;
#pragma unroll
    for (int i = 0; i < 4; ++i) {
        int r0 = m0 + m_w + i*16 + g;
        int r1 = r0 + 8;
#pragma unroll
        for (int j = 0; j < 4; ++j) {
            int col = n_w + j*8 + tg*2;
            if (r0 < NPIX) *(float2*)(Ob + (size_t)r0*IDIM + col) = make_float2(acc[i][j][0], acc[i][j][1]);
            if (r1 < NPIX) *(float2*)(Ob + (size_t)r1*IDIM + col) = make_float2(acc[i][j][2], acc[i][j][3]);
        }
    }
}

// ---------------- packed fp32x2 FMA (small fp32 GEMMs) ---------------------
#define FMA2(d,a,b) asm("fma.rn.f32x2 %0, %1, %2, %0;" : "+l"(d) : "l"(a), "l"(b))
#define PACK2(d,x)  asm("mov.b64 %0, {%1, %1};" : "=l"(d) : "f"(x))

__device__ __forceinline__ void mma_tile(const float (*As)[132], const float (*Bs)[132],
                                         int ty, int tx, unsigned long long acc[8][4])
{
#pragma unroll
    for (int k = 0; k < 16; ++k) {
        float4 a0 = *(const float4*)&As[k][ty*4];
        float4 a1 = *(const float4*)&As[k][64 + ty*4];
        unsigned long long b0 = *(const unsigned long long*)&Bs[k][tx*4];
        unsigned long long b1 = *(const unsigned long long*)&Bs[k][tx*4 + 2];
        unsigned long long b2 = *(const unsigned long long*)&Bs[k][64 + tx*4];
        unsigned long long b3 = *(const unsigned long long*)&Bs[k][64 + tx*4 + 2];
        float av[8] = {a0.x,a0.y,a0.z,a0.w,a1.x,a1.y,a1.z,a1.w};
#pragma unroll
        for (int i = 0; i < 8; ++i) {
            unsigned long long ap;
            PACK2(ap, av[i]);
            FMA2(acc[i][0], ap, b0);
            FMA2(acc[i][1], ap, b1);
            FMA2(acc[i][2], ap, b2);
            FMA2(acc[i][3], ap, b3);
        }
    }
}

// ============================================================================
// fp32 NN GEMM (g projection + final epilogue)
// ============================================================================
__global__ void __launch_bounds__(256)
sgemm_nn(const float* __restrict__ A, const float* __restrict__ B, float* __restrict__ C,
         int M, int N, int K, const float* __restrict__ resid)
{
    __shared__ float As[16][132];
    __shared__ float Bs[16][132];
    const int m0 = blockIdx.y * 128;
    const int n0 = blockIdx.x * 128;
    const int t  = threadIdx.x;
    const int tx = t & 15, ty = t >> 4;

    unsigned long long acc[8][4];
#pragma unroll
    for (int i = 0; i < 8; ++i)
#pragma unroll
        for (int j = 0; j < 4; ++j) acc[i][j] = 0ull;

    float4 aReg[2], bReg[2];
    const int nk = K >> 4;

#pragma unroll
    for (int s = 0; s < 2; ++s) {
        int id = t + s*256;
        int r = id >> 2, c4 = id & 3;
        int gr = m0 + r;
        aReg[s] = (gr < M) ? *(const float4*)(A + (long long)gr*K + c4*4)
                           : make_float4(0.f,0.f,0.f,0.f);
        int kr = id >> 5, c = id & 31;
        bReg[s] = *(const float4*)(B + (long long)kr*N + n0 + c*4);
    }

    for (int kc = 0; kc < nk; ++kc) {
#pragma unroll
        for (int s = 0; s < 2; ++s) {
            int id = t + s*256;
            int r = id >> 2, c4 = id & 3;
            As[c4*4+0][r] = aReg[s].x; As[c4*4+1][r] = aReg[s].y;
            As[c4*4+2][r] = aReg[s].z; As[c4*4+3][r] = aReg[s].w;
            int kr = id >> 5, c = id & 31;
            *(float4*)&Bs[kr][c*4] = bReg[s];
        }
        __syncthreads();
        if (kc + 1 < nk) {
            const int k0 = (kc + 1) * 16;
#pragma unroll
            for (int s = 0; s < 2; ++s) {
                int id = t + s*256;
                int r = id >> 2, c4 = id & 3;
                int gr = m0 + r;
                aReg[s] = (gr < M) ? *(const float4*)(A + (long long)gr*K + k0 + c4*4)
                                   : make_float4(0.f,0.f,0.f,0.f);
                int kr = id >> 5, c = id & 31;
                bReg[s] = *(const float4*)(B + (long long)(k0+kr)*N + n0 + c*4);
            }
        }
        mma_tile(As, Bs, ty, tx, acc);
        __syncthreads();
    }

#pragma unroll
    for (int i = 0; i < 8; ++i) {
        int r  = (i < 4) ? (ty*4 + i) : (64 + ty*4 + (i-4));
        int gr = m0 + r;
        if (gr >= M) continue;
        float* Cr = C + (long long)gr*N + n0;
        float2 p0 = *(float2*)&acc[i][0];
        float2 p1 = *(float2*)&acc[i][1];
        float2 p2 = *(float2*)&acc[i][2];
        float2 p3 = *(float2*)&acc[i][3];
        float4 v0 = make_float4(p0.x, p0.y, p1.x, p1.y);
        float4 v1 = make_float4(p2.x, p2.y, p3.x, p3.y);
        if (resid) {
            const float* Rr = resid + (long long)gr*N + n0;
            float4 r0 = *(const float4*)(Rr + tx*4);
            float4 r1 = *(const float4*)(Rr + 64 + tx*4);
            v0.x += r0.x; v0.y += r0.y; v0.z += r0.z; v0.w += r0.w;
            v1.x += r1.x; v1.y += r1.y; v1.z += r1.z; v1.w += r1.w;
        }
        *(float4*)(Cr + tx*4)      = v0;
        *(float4*)(Cr + 64 + tx*4) = v1;
    }
}

// ============================================================================
// Projection + 3-way split -> extended-K bf16 layout.
// blockIdx.z: 0 = theta (ext: h,h,m,m,h,l), 1 = phi (ext: h,m,h,m,l,h).
// ============================================================================
__device__ __forceinline__ void split3(float a, bf16& h, bf16& m, bf16& l) {
    h = __float2bfloat16(a); float r  = a - __bfloat162float(h);
    m = __float2bfloat16(r); float r2 = r - __bfloat162float(m);
    l = __float2bfloat16(r2);
}

__global__ void __launch_bounds__(256)
proj_split(const float* __restrict__ A,
           const float* __restrict__ Bth, const float* __restrict__ Bph,
           bf16* __restrict__ THX, bf16* __restrict__ PHX, int M, int K)
{
    const int N = IDIM;
    const float* B = blockIdx.z ? Bph : Bth;
    bf16* EXT = blockIdx.z ? PHX : THX;
    int ph0, ph1, ph2, pm0, pm1, pl0;
    if (blockIdx.z == 0) { ph0=0; ph1=128; ph2=512; pm0=256; pm1=384; pl0=640; }
    else                 { ph0=0; ph1=256; ph2=640; pm0=128; pm1=384; pl0=512; }

    __shared__ float As[16][132];
    __shared__ float Bs[16][132];
    const int m0 = blockIdx.y * 128;
    const int t  = threadIdx.x;
    const int tx = t & 15, ty = t >> 4;

    unsigned long long acc[8][4];
#pragma unroll
    for (int i = 0; i < 8; ++i)
#pragma unroll
        for (int j = 0; j < 4; ++j) acc[i][j] = 0ull;

    float4 aReg[2], bReg[2];
    const int nk = K >> 4;

#pragma unroll
    for (int s = 0; s < 2; ++s) {
        int id = t + s*256;
        int r = id >> 2, c4 = id & 3;
        int gr = m0 + r;
        aReg[s] = (gr < M) ? *(const float4*)(A + (long long)gr*K + c4*4)
                           : make_float4(0.f,0.f,0.f,0.f);
        int kr = id >> 5, c = id & 31;
        bReg[s] = *(const float4*)(B + (long long)kr*N + c*4);
    }

    for (int kc = 0; kc < nk; ++kc) {
#pragma unroll
        for (int s = 0; s < 2; ++s) {
            int id = t + s*256;
            int r = id >> 2, c4 = id & 3;
            As[c4*4+0][r] = aReg[s].x; As[c4*4+1][r] = aReg[s].y;
            As[c4*4+2][r] = aReg[s].z; As[c4*4+3][r] = aReg[s].w;
            int kr = id >> 5, c = id & 31;
            *(float4*)&Bs[kr][c*4] = bReg[s];
        }
        __syncthreads();
        if (kc + 1 < nk) {
            const int k0 = (kc + 1) * 16;
#pragma unroll
            for (int s = 0; s < 2; ++s) {
                int id = t + s*256;
                int r = id >> 2, c4 = id & 3;
                int gr = m0 + r;
                aReg[s] = (gr < M) ? *(const float4*)(A + (long long)gr*K + k0 + c4*4)
                                   : make_float4(0.f,0.f,0.f,0.f);
                int kr = id >> 5, c = id & 31;
                bReg[s] = *(const float4*)(B + (long long)(k0+kr)*N + c*4);
            }
        }
        mma_tile(As, Bs, ty, tx, acc);
        __syncthreads();
    }

#pragma unroll
    for (int i = 0; i < 8; ++i) {
        int r  = (i < 4) ? (ty*4 + i) : (64 + ty*4 + (i-4));
        int gr = m0 + r;
        if (gr >= M) continue;
        float2 p0 = *(float2*)&acc[i][0];
        float2 p1 = *(float2*)&acc[i][1];
        float2 p2 = *(float2*)&acc[i][2];
        float2 p3 = *(float2*)&acc[i][3];
        float vals[8] = {p0.x, p0.y, p1.x, p1.y, p2.x, p2.y, p3.x, p3.y};
        bf16* rowp = EXT + (size_t)gr*KEXT;
#pragma unroll
        for (int grp = 0; grp < 2; ++grp) {
            union { bf16 h[4]; uint2 u; } uh, um, ul;
#pragma unroll
            for (int j = 0; j < 4; ++j)
                split3(vals[grp*4 + j], uh.h[j], um.h[j], ul.h[j]);
            int col = grp*64 + tx*4;
            *(uint2*)(rowp + ph0 + col) = uh.u;
            *(uint2*)(rowp + ph1 + col) = uh.u;
            *(uint2*)(rowp + ph2 + col) = uh.u;
            *(uint2*)(rowp + pm0 + col) = um.u;
            *(uint2*)(rowp + pm1 + col) = um.u;
            *(uint2*)(rowp + pl0 + col) = ul.u;
        }
    }
}

// ============================================================================
// g transpose + 2-way bf16 split: g[B*N,I] -> gt0/gt1 [B][I][N]
// ============================================================================
__global__ void __launch_bounds__(256)
transpose_split(const float* __restrict__ g, bf16* __restrict__ t0, bf16* __restrict__ t1)
{
    __shared__ float tile[32][33];
    const int b = blockIdx.z, n0 = blockIdx.x*32, i0 = blockIdx.y*32;
    const int lane = threadIdx.x & 31, wrow = threadIdx.x >> 5;
#pragma unroll
    for (int rr = 0; rr < 4; ++rr) {
        int n = n0 + wrow + rr*8;
        tile[wrow + rr*8][lane] = g[((size_t)b*NPIX + n)*IDIM + i0 + lane];
    }
    __syncthreads();
#pragma unroll
    for (int rr = 0; rr < 4; ++rr) {
        int i = i0 + wrow + rr*8;
        int n = n0 + lane;
        float a = tile[lane][wrow + rr*8];
        bf16 h = __float2bfloat16(a);
        bf16 l = __float2bfloat16(a - __bfloat162float(h));
        size_t o = ((size_t)b*IDIM + i)*NPIX + n;
        t0[o] = h; t1[o] = l;
    }
}

// ============================================================================
// Row softmax in place; also emits bf16 hi/lo splits of w.
// ============================================================================
__global__ void __launch_bounds__(256)
softmax_rows(float* __restrict__ W, bf16* __restrict__ Whi, bf16* __restrict__ Wlo)
{
    __shared__ float4 buf4[NPIX/4];
    __shared__ float  red[8];
    const size_t row = blockIdx.x;
    float* p = W + row * NPIX;
    bf16* ph = Whi + row * NPIX;
    bf16* pl = Wlo + row * NPIX;
    const int t = threadIdx.x;

    float m = -3.402823466e38f;
    for (int i = t; i < NPIX/4; i += 256) {
        float4 v = *(const float4*)(p + i*4);
        buf4[i] = v;
        m = fmaxf(m, fmaxf(fmaxf(v.x, v.y), fmaxf(v.z, v.w)));
    }
#pragma unroll
    for (int o = 16; o > 0; o >>= 1) m = fmaxf(m, __shfl_xor_sync(0xffffffffu, m, o));
    if ((t & 31) == 0) red[t >> 5] = m;
    __syncthreads();
    float bm = red[0];
#pragma unroll
    for (int wv = 1; wv < 8; ++wv) bm = fmaxf(bm, red[wv]);
    __syncthreads();

    float s = 0.f;
    for (int i = t; i < NPIX/4; i += 256) {
        float4 v = buf4[i];
        v.x = __expf(v.x - bm); v.y = __expf(v.y - bm);
        v.z = __expf(v.z - bm); v.w = __expf(v.w - bm);
        buf4[i] = v;
        s += (v.x + v.y) + (v.z + v.w);
    }
#pragma unroll
    for (int o = 16; o > 0; o >>= 1) s += __shfl_xor_sync(0xffffffffu, s, o);
    if ((t & 31) == 0) red[t >> 5] = s;
    __syncthreads();
    float bs = red[0];
#pragma unroll
    for (int wv = 1; wv < 8; ++wv) bs += red[wv];
    const float inv = 1.0f / bs;

    for (int i = t; i < NPIX/4; i += 256) {
        float4 v = buf4[i];
        v.x *= inv; v.y *= inv; v.z *= inv; v.w *= inv;
        *(float4*)(p + i*4) = v;
        union { bf16 h[4]; uint2 u; } H, L;
        H.h[0] = __float2bfloat16(v.x); L.h[0] = __float2bfloat16(v.x - __bfloat162float(H.h[0]));
        H.h[1] = __float2bfloat16(v.y); L.h[1] = __float2bfloat16(v.y - __bfloat162float(H.h[1]));
        H.h[2] = __float2bfloat16(v.z); L.h[2] = __float2bfloat16(v.z - __bfloat162float(H.h[2]));
        H.h[3] = __float2bfloat16(v.w); L.h[3] = __float2bfloat16(v.w - __bfloat162float(H.h[3]));
        *(uint2*)(ph + i*4) = H.u;
        *(uint2*)(pl + i*4) = L.u;
    }
}

// ============================================================================
extern "C" void kernel_launch(void* const* d_in, const int* in_sizes, int n_in,
                              void* d_out, int out_size)
{
    const float* x   = (const float*)d_in[0];
    const float* wth = (const float*)d_in[1];
    const float* wph = (const float*)d_in[2];
    const float* wgv = (const float*)d_in[3];
    const float* wo  = (const float*)d_in[4];
    float* out0 = (float*)d_out;
    float* W    = out0 + (long long)OUT0;

    float *gv, *ov;
    bf16 *thx, *phx, *gt0, *gt1, *whi, *wlo;
    cudaGetSymbolAddress((void**)&gv,  g_gval);
    cudaGetSymbolAddress((void**)&ov,  g_oval);
    cudaGetSymbolAddress((void**)&thx, g_thx);
    cudaGetSymbolAddress((void**)&phx, g_phx);
    cudaGetSymbolAddress((void**)&gt0, g_gt0);
    cudaGetSymbolAddress((void**)&gt1, g_gt1);
    cudaGetSymbolAddress((void**)&whi, g_whi);
    cudaGetSymbolAddress((void**)&wlo, g_wlo);

    dim3 blk(256);

    // 1) theta+phi projections with ext-split epilogue; g projection fp32
    proj_split<<<dim3(1, 196, 2), blk>>>(x, wth, wph, thx, phx, BATCH*NPIX, CDIM);
    sgemm_nn<<<dim3(1, 196, 1), blk>>>(x, wgv, gv, BATCH*NPIX, IDIM, CDIM, nullptr);

    // 2) g transpose + 2-way split
    transpose_split<<<dim3(98, 4, 8), blk>>>(gv, gt0, gt1);

    // 3) logits = thx @ phx^T  (ext K=768, bf16 HMMA, 2-stage pipe) -> w region
    gemm_nt_bf16<<<dim3(25, 25, 8), blk>>>(thx, phx, W, NPIX, NPIX, KEXT,
                                           (long)NPIX*KEXT, (long)NPIX*KEXT,
                                           (long)NPIX*NPIX);

    // 4) softmax rows in place + emit bf16 splits
    softmax_rows<<<BATCH*NPIX, 256>>>(W, whi, wlo);

    // 5) o = w @ g (bf16 HMMA, 3 combos, 2-stage pipe)
    ogemm_mma<<<dim3(25, 8), blk>>>(whi, wlo, gt0, gt1, ov);

    // 6) out = o @ w_o + x
    sgemm_nn<<<dim3(2, 196, 1), blk>>>(ov, wo, out0, BATCH*NPIX, CDIM, IDIM, x);
}

// round 9
// speedup vs baseline: 1.6554x; 1.2059x over previous
#include <cuda_runtime.h>
#include <cuda_bf16.h>
#include <cstdint>

#define BATCH 8
#define NPIX  3136
#define CDIM  256
#define IDIM  128
#define KEXT  384           // 3 combos x 128: theta=[h,h,m], phi=[h,m,h]
#define OUT0  (BATCH*NPIX*CDIM)

typedef __nv_bfloat16 bf16;

// ---------------- scratch (__device__ globals; no allocation allowed) ------
static __device__ __align__(16) float g_gval[BATCH*NPIX*IDIM];
static __device__ __align__(16) float g_oval[BATCH*NPIX*IDIM];
static __device__ __align__(16) bf16  g_thx[(size_t)BATCH*NPIX*KEXT];  // theta ext splits
static __device__ __align__(16) bf16  g_phx[(size_t)BATCH*NPIX*KEXT];  // phi   ext splits
static __device__ __align__(16) bf16  g_gt0[BATCH*IDIM*NPIX];          // g^T hi
static __device__ __align__(16) bf16  g_gt1[BATCH*IDIM*NPIX];          // g^T lo
static __device__ __align__(16) bf16  g_whi[(size_t)BATCH*NPIX*NPIX];  // softmax hi
static __device__ __align__(16) bf16  g_wlo[(size_t)BATCH*NPIX*NPIX];  // softmax lo

// ---------------- PTX helpers ----------------------------------------------
__device__ __forceinline__ uint32_t smem_u32(const void* p) {
    uint32_t a;
    asm("{ .reg .u64 t; cvta.to.shared.u64 t, %1; cvt.u32.u64 %0, t; }" : "=r"(a) : "l"(p));
    return a;
}
__device__ __forceinline__ void cp_async16(uint32_t dst, const void* src) {
    unsigned long long gsrc = __cvta_generic_to_global(const_cast<void*>(src));
    asm volatile("cp.async.cg.shared.global [%0], [%1], 16;" :: "r"(dst), "l"(gsrc) : "memory");
}
#define CP_COMMIT()        asm volatile("cp.async.commit_group;" ::: "memory")
#define CP_WAIT1()         asm volatile("cp.async.wait_group 1;" ::: "memory")
#define CP_WAIT0()         asm volatile("cp.async.wait_group 0;" ::: "memory")

__device__ __forceinline__ void ldsm4(uint32_t& r0, uint32_t& r1, uint32_t& r2, uint32_t& r3,
                                      uint32_t addr) {
    asm volatile("ldmatrix.sync.aligned.m8n8.x4.shared.b16 {%0,%1,%2,%3}, [%4];"
                 : "=r"(r0), "=r"(r1), "=r"(r2), "=r"(r3) : "r"(addr));
}
__device__ __forceinline__ void mma_bf16(float* c, const uint32_t* a, const uint32_t* b) {
    asm volatile("mma.sync.aligned.m16n8k16.row.col.f32.bf16.bf16.f32 "
                 "{%0,%1,%2,%3}, {%4,%5,%6,%7}, {%8,%9}, {%0,%1,%2,%3};"
                 : "+f"(c[0]), "+f"(c[1]), "+f"(c[2]), "+f"(c[3])
                 : "r"(a[0]), "r"(a[1]), "r"(a[2]), "r"(a[3]), "r"(b[0]), "r"(b[1]));
}

// swizzle for 128/64/32-byte row tiles
template<int ROWB>
__device__ __forceinline__ uint32_t swz(uint32_t off) {
    const uint32_t mask = (ROWB == 128) ? 0x70u : (ROWB == 64) ? 0x30u : 0x10u;
    return off ^ ((off >> 3) & mask);
}

// 128-row x (ROWB bytes) tile loader via cp.async, row clamp.
template<int ROWB>
__device__ __forceinline__ void load_tile(uint32_t sbase, const char* gsrc,
                                          long rowStride, int maxRow, int tid) {
    const int CPR = ROWB / 16;          // 16B chunks per row
    const int TOT = 128 * CPR;          // total chunks
#pragma unroll
    for (int i = 0; i < TOT/256; ++i) {
        int idx = tid + i*256;
        int r = idx / CPR, cq = idx % CPR;
        int rr = r < maxRow ? r : maxRow - 1;
        const char* src = gsrc + (long)rr*rowStride + cq*16;
        cp_async16(sbase + swz<ROWB>(r*ROWB + cq*16), src);
    }
}

// Per-warp fragment loads (A: 4 m16 tiles, B: 4 n8 tiles) for one k16 step.
template<int ROWB>
__device__ __forceinline__ void lds_afrag(uint32_t abase, int m_w, int ks, int lane,
                                          uint32_t Af[4][4]) {
    int q = lane >> 3;
#pragma unroll
    for (int i = 0; i < 4; ++i) {
        int row = m_w + i*16 + ((q & 1) << 3) + (lane & 7);
        int col = ks*32 + ((q >> 1) << 4);
        ldsm4(Af[i][0], Af[i][1], Af[i][2], Af[i][3], abase + swz<ROWB>(row*ROWB + col));
    }
}
template<int ROWB>
__device__ __forceinline__ void lds_bfrag(uint32_t bbase, int n_w, int ks, int lane,
                                          uint32_t Bf[4][2]) {
    int q = lane >> 3;
#pragma unroll
    for (int jj = 0; jj < 2; ++jj) {
        int row = n_w + jj*16 + ((q >> 1) << 3) + (lane & 7);
        int col = ks*32 + ((q & 1) << 4);
        ldsm4(Bf[jj*2][0], Bf[jj*2][1], Bf[jj*2+1][0], Bf[jj*2+1][1],
              bbase + swz<ROWB>(row*ROWB + col));
    }
}

// ============================================================================
// bf16 NT GEMM via mma.sync: C[M,N] = A[M,K]·B[N,K]^T, K mult of 32.
// Block 128x128, 8 warps, warp tile 64x32.
// 2-stage cp.async double buffer, K-chunk 32 (64B rows), 32KB static smem.
// ============================================================================
__global__ void __launch_bounds__(256)
gemm_nt_bf16(const bf16* __restrict__ A, const bf16* __restrict__ B, float* __restrict__ C,
             int M, int N, int Kext, long sA, long sB, long sC)
{
    __shared__ __align__(128) char smbuf[32768];   // 2 stages x (8KB A + 8KB B)
    const uint32_t sb = smem_u32(smbuf);
    const int tid = threadIdx.x, lane = tid & 31, wid = tid >> 5;
    const int m_w = (wid & 1)*64, n_w = (wid >> 1)*32;
    const int b = blockIdx.z, m0 = blockIdx.y*128, n0 = blockIdx.x*128;
    const char* Ab = (const char*)(A + (size_t)b*sA) + (size_t)m0*Kext*2;
    const char* Bb = (const char*)(B + (size_t)b*sB) + (size_t)n0*Kext*2;
    const long rsA = (long)Kext*2;
    const int  mRem = M - m0, nRem = N - n0;
    const int  nc = Kext >> 5;          // chunks of 32 (12 for KEXT=384)

    float acc[4][4][4];
#pragma unroll
    for (int i = 0; i < 4; ++i)
#pragma unroll
        for (int j = 0; j < 4; ++j)
#pragma unroll
            for (int v = 0; v < 4; ++v) acc[i][j][v] = 0.f;

    // stage s base = sb + s*16384; A at +0 (8KB), B at +8192
    load_tile<64>(sb,        Ab, rsA, mRem, tid);
    load_tile<64>(sb + 8192, Bb, rsA, nRem, tid);
    CP_COMMIT();

    for (int c = 0; c < nc; ++c) {
        if (c + 1 < nc) {
            uint32_t s1 = ((c + 1) & 1) * 16384u;
            load_tile<64>(sb + s1,        Ab + (long)(c+1)*64, rsA, mRem, tid);
            load_tile<64>(sb + s1 + 8192, Bb + (long)(c+1)*64, rsA, nRem, tid);
            CP_COMMIT();
            CP_WAIT1();
        } else {
            CP_WAIT0();
        }
        __syncthreads();
        uint32_t abase = sb + (uint32_t)(c & 1)*16384u;
        uint32_t bbase = abase + 8192;
        uint32_t Af[4][4], Bf[4][2];
#pragma unroll
        for (int ks = 0; ks < 2; ++ks) {
            lds_afrag<64>(abase, m_w, ks, lane, Af);
            lds_bfrag<64>(bbase, n_w, ks, lane, Bf);
#pragma unroll
            for (int i = 0; i < 4; ++i)
#pragma unroll
                for (int j = 0; j < 4; ++j)
                    mma_bf16(acc[i][j], Af[i], Bf[j]);
        }
        __syncthreads();
    }

    float* Cb = C + (size_t)b*sC;
    const int g = lane >> 2, tg = lane & 3;
#pragma unroll
    for (int i = 0; i < 4; ++i) {
        int r0 = m0 + m_w + i*16 + g;
        int r1 = r0 + 8;
#pragma unroll
        for (int j = 0; j < 4; ++j) {
            int col = n0 + n_w + j*8 + tg*2;
            if (col < N) {
                if (r0 < M) *(float2*)(Cb + (size_t)r0*N + col) = make_float2(acc[i][j][0], acc[i][j][1]);
                if (r1 < M) *(float2*)(Cb + (size_t)r1*N + col) = make_float2(acc[i][j][2], acc[i][j][3]);
            }
        }
    }
}

// ============================================================================
// o = w·g via mma.sync, 3 combos/chunk: whi·ghi + whi·glo + wlo·ghi.
// Block 128(m) x 128(n=i). 2-stage double buffer, K-chunk 16 (32B rows), 32KB.
// grid (25, 8).
// ============================================================================
__global__ void __launch_bounds__(256)
ogemm_mma(const bf16* __restrict__ Whi, const bf16* __restrict__ Wlo,
          const bf16* __restrict__ Gh,  const bf16* __restrict__ Gl,
          float* __restrict__ Ov)
{
    __shared__ __align__(128) char smbuf[32768];   // 2 stages x (4 tiles x 4KB)
    const uint32_t sb = smem_u32(smbuf);
    const int tid = threadIdx.x, lane = tid & 31, wid = tid >> 5;
    const int m_w = (wid & 1)*64, n_w = (wid >> 1)*32;
    const int b = blockIdx.y, m0 = blockIdx.x*128;
    const long rsW = (long)NPIX*2;
    const char* Ah = (const char*)(Whi + ((size_t)b*NPIX + m0)*NPIX);
    const char* Al = (const char*)(Wlo + ((size_t)b*NPIX + m0)*NPIX);
    const char* Bh = (const char*)(Gh + (size_t)b*IDIM*NPIX);
    const char* Bl = (const char*)(Gl + (size_t)b*IDIM*NPIX);
    const int mRem = NPIX - m0;
    const int nc = NPIX / 16;   // 196 chunks of K=16

    float acc[4][4][4];
#pragma unroll
    for (int i = 0; i < 4; ++i)
#pragma unroll
        for (int j = 0; j < 4; ++j)
#pragma unroll
            for (int v = 0; v < 4; ++v) acc[i][j][v] = 0.f;

    // stage layout (16KB): [whi 4KB][wlo 4KB][ghi 4KB][glo 4KB]
    {
        load_tile<32>(sb,         Ah, rsW, mRem, tid);
        load_tile<32>(sb +  4096, Al, rsW, mRem, tid);
        load_tile<32>(sb +  8192, Bh, rsW, 128,  tid);
        load_tile<32>(sb + 12288, Bl, rsW, 128,  tid);
        CP_COMMIT();
    }

    for (int c = 0; c < nc; ++c) {
        if (c + 1 < nc) {
            uint32_t s1 = sb + (uint32_t)((c + 1) & 1)*16384u;
            const long kb = (long)(c+1)*32;
            load_tile<32>(s1,         Ah + kb, rsW, mRem, tid);
            load_tile<32>(s1 +  4096, Al + kb, rsW, mRem, tid);
            load_tile<32>(s1 +  8192, Bh + kb, rsW, 128,  tid);
            load_tile<32>(s1 + 12288, Bl + kb, rsW, 128,  tid);
            CP_COMMIT();
            CP_WAIT1();
        } else {
            CP_WAIT0();
        }
        __syncthreads();
        uint32_t base = sb + (uint32_t)(c & 1)*16384u;
        uint32_t Af[4][4], Bg[4][2], Bl2[4][2];
        lds_afrag<32>(base,          m_w, 0, lane, Af);     // whi
        lds_bfrag<32>(base +  8192,  n_w, 0, lane, Bg);     // ghi
        lds_bfrag<32>(base + 12288,  n_w, 0, lane, Bl2);    // glo
#pragma unroll
        for (int i = 0; i < 4; ++i)
#pragma unroll
            for (int j = 0; j < 4; ++j) {
                mma_bf16(acc[i][j], Af[i], Bg[j]);
                mma_bf16(acc[i][j], Af[i], Bl2[j]);
            }
        lds_afrag<32>(base + 4096, m_w, 0, lane, Af);       // wlo
#pragma unroll
        for (int i = 0; i < 4; ++i)
#pragma unroll
            for (int j = 0; j < 4; ++j)
                mma_bf16(acc[i][j], Af[i], Bg[j]);
        __syncthreads();
    }

    float* Ob = Ov + (size_t)b*NPIX*IDIM;
    const int g = lane >> 2, tg = lane & 3;
#pragma unroll
    for (int i = 0; i < 4; ++i) {
        int r0 = m0 + m_w + i*16 + g;
        int r1 = r0 + 8;
#pragma unroll
        for (int j = 0; j < 4; ++j) {
            int col = n_w + j*8 + tg*2;
            if (r0 < NPIX) *(float2*)(Ob + (size_t)r0*IDIM + col) = make_float2(acc[i][j][0], acc[i][j][1]);
            if (r1 < NPIX) *(float2*)(Ob + (size_t)r1*IDIM + col) = make_float2(acc[i][j][2], acc[i][j][3]);
        }
    }
}

// ---------------- packed fp32x2 FMA (small fp32 GEMMs) ---------------------
#define FMA2(d,a,b) asm("fma.rn.f32x2 %0, %1, %2, %0;" : "+l"(d) : "l"(a), "l"(b))
#define PACK2(d,x)  asm("mov.b64 %0, {%1, %1};" : "=l"(d) : "f"(x))

__device__ __forceinline__ void mma_tile(const float (*As)[132], const float (*Bs)[132],
                                         int ty, int tx, unsigned long long acc[8][4])
{
#pragma unroll
    for (int k = 0; k < 16; ++k) {
        float4 a0 = *(const float4*)&As[k][ty*4];
        float4 a1 = *(const float4*)&As[k][64 + ty*4];
        unsigned long long b0 = *(const unsigned long long*)&Bs[k][tx*4];
        unsigned long long b1 = *(const unsigned long long*)&Bs[k][tx*4 + 2];
        unsigned long long b2 = *(const unsigned long long*)&Bs[k][64 + tx*4];
        unsigned long long b3 = *(const unsigned long long*)&Bs[k][64 + tx*4 + 2];
        float av[8] = {a0.x,a0.y,a0.z,a0.w,a1.x,a1.y,a1.z,a1.w};
#pragma unroll
        for (int i = 0; i < 8; ++i) {
            unsigned long long ap;
            PACK2(ap, av[i]);
            FMA2(acc[i][0], ap, b0);
            FMA2(acc[i][1], ap, b1);
            FMA2(acc[i][2], ap, b2);
            FMA2(acc[i][3], ap, b3);
        }
    }
}

// ============================================================================
// fp32 NN GEMM (g projection + final epilogue)
// ============================================================================
__global__ void __launch_bounds__(256)
sgemm_nn(const float* __restrict__ A, const float* __restrict__ B, float* __restrict__ C,
         int M, int N, int K, const float* __restrict__ resid)
{
    __shared__ float As[16][132];
    __shared__ float Bs[16][132];
    const int m0 = blockIdx.y * 128;
    const int n0 = blockIdx.x * 128;
    const int t  = threadIdx.x;
    const int tx = t & 15, ty = t >> 4;

    unsigned long long acc[8][4];
#pragma unroll
    for (int i = 0; i < 8; ++i)
#pragma unroll
        for (int j = 0; j < 4; ++j) acc[i][j] = 0ull;

    float4 aReg[2], bReg[2];
    const int nk = K >> 4;

#pragma unroll
    for (int s = 0; s < 2; ++s) {
        int id = t + s*256;
        int r = id >> 2, c4 = id & 3;
        int gr = m0 + r;
        aReg[s] = (gr < M) ? *(const float4*)(A + (long long)gr*K + c4*4)
                           : make_float4(0.f,0.f,0.f,0.f);
        int kr = id >> 5, c = id & 31;
        bReg[s] = *(const float4*)(B + (long long)kr*N + n0 + c*4);
    }

    for (int kc = 0; kc < nk; ++kc) {
#pragma unroll
        for (int s = 0; s < 2; ++s) {
            int id = t + s*256;
            int r = id >> 2, c4 = id & 3;
            As[c4*4+0][r] = aReg[s].x; As[c4*4+1][r] = aReg[s].y;
            As[c4*4+2][r] = aReg[s].z; As[c4*4+3][r] = aReg[s].w;
            int kr = id >> 5, c = id & 31;
            *(float4*)&Bs[kr][c*4] = bReg[s];
        }
        __syncthreads();
        if (kc + 1 < nk) {
            const int k0 = (kc + 1) * 16;
#pragma unroll
            for (int s = 0; s < 2; ++s) {
                int id = t + s*256;
                int r = id >> 2, c4 = id & 3;
                int gr = m0 + r;
                aReg[s] = (gr < M) ? *(const float4*)(A + (long long)gr*K + k0 + c4*4)
                                   : make_float4(0.f,0.f,0.f,0.f);
                int kr = id >> 5, c = id & 31;
                bReg[s] = *(const float4*)(B + (long long)(k0+kr)*N + n0 + c*4);
            }
        }
        mma_tile(As, Bs, ty, tx, acc);
        __syncthreads();
    }

#pragma unroll
    for (int i = 0; i < 8; ++i) {
        int r  = (i < 4) ? (ty*4 + i) : (64 + ty*4 + (i-4));
        int gr = m0 + r;
        if (gr >= M) continue;
        float* Cr = C + (long long)gr*N + n0;
        float2 p0 = *(float2*)&acc[i][0];
        float2 p1 = *(float2*)&acc[i][1];
        float2 p2 = *(float2*)&acc[i][2];
        float2 p3 = *(float2*)&acc[i][3];
        float4 v0 = make_float4(p0.x, p0.y, p1.x, p1.y);
        float4 v1 = make_float4(p2.x, p2.y, p3.x, p3.y);
        if (resid) {
            const float* Rr = resid + (long long)gr*N + n0;
            float4 r0 = *(const float4*)(Rr + tx*4);
            float4 r1 = *(const float4*)(Rr + 64 + tx*4);
            v0.x += r0.x; v0.y += r0.y; v0.z += r0.z; v0.w += r0.w;
            v1.x += r1.x; v1.y += r1.y; v1.z += r1.z; v1.w += r1.w;
        }
        *(float4*)(Cr + tx*4)      = v0;
        *(float4*)(Cr + 64 + tx*4) = v1;
    }
}

// ============================================================================
// Projection + 2-way split -> extended-K bf16 layout (3 blocks of 128).
// blockIdx.z: 0 = theta (ext: h,h,m), 1 = phi (ext: h,m,h).
// ============================================================================
__device__ __forceinline__ void split2(float a, bf16& h, bf16& m) {
    h = __float2bfloat16(a); float r = a - __bfloat162float(h);
    m = __float2bfloat16(r);
}

__global__ void __launch_bounds__(256)
proj_split(const float* __restrict__ A,
           const float* __restrict__ Bth, const float* __restrict__ Bph,
           bf16* __restrict__ THX, bf16* __restrict__ PHX, int M, int K)
{
    const int N = IDIM;
    const float* B = blockIdx.z ? Bph : Bth;
    bf16* EXT = blockIdx.z ? PHX : THX;
    // hi/mid block placements (element offsets within KEXT=384 row)
    int ph0, ph1, pm0;
    if (blockIdx.z == 0) { ph0 = 0; ph1 = 128; pm0 = 256; }   // theta: h,h,m
    else                 { ph0 = 0; ph1 = 256; pm0 = 128; }   // phi:   h,m,h

    __shared__ float As[16][132];
    __shared__ float Bs[16][132];
    const int m0 = blockIdx.y * 128;
    const int t  = threadIdx.x;
    const int tx = t & 15, ty = t >> 4;

    unsigned long long acc[8][4];
#pragma unroll
    for (int i = 0; i < 8; ++i)
#pragma unroll
        for (int j = 0; j < 4; ++j) acc[i][j] = 0ull;

    float4 aReg[2], bReg[2];
    const int nk = K >> 4;

#pragma unroll
    for (int s = 0; s < 2; ++s) {
        int id = t + s*256;
        int r = id >> 2, c4 = id & 3;
        int gr = m0 + r;
        aReg[s] = (gr < M) ? *(const float4*)(A + (long long)gr*K + c4*4)
                           : make_float4(0.f,0.f,0.f,0.f);
        int kr = id >> 5, c = id & 31;
        bReg[s] = *(const float4*)(B + (long long)kr*N + c*4);
    }

    for (int kc = 0; kc < nk; ++kc) {
#pragma unroll
        for (int s = 0; s < 2; ++s) {
            int id = t + s*256;
            int r = id >> 2, c4 = id & 3;
            As[c4*4+0][r] = aReg[s].x; As[c4*4+1][r] = aReg[s].y;
            As[c4*4+2][r] = aReg[s].z; As[c4*4+3][r] = aReg[s].w;
            int kr = id >> 5, c = id & 31;
            *(float4*)&Bs[kr][c*4] = bReg[s];
        }
        __syncthreads();
        if (kc + 1 < nk) {
            const int k0 = (kc + 1) * 16;
#pragma unroll
            for (int s = 0; s < 2; ++s) {
                int id = t + s*256;
                int r = id >> 2, c4 = id & 3;
                int gr = m0 + r;
                aReg[s] = (gr < M) ? *(const float4*)(A + (long long)gr*K + k0 + c4*4)
                                   : make_float4(0.f,0.f,0.f,0.f);
                int kr = id >> 5, c = id & 31;
                bReg[s] = *(const float4*)(B + (long long)(k0+kr)*N + c*4);
            }
        }
        mma_tile(As, Bs, ty, tx, acc);
        __syncthreads();
    }

#pragma unroll
    for (int i = 0; i < 8; ++i) {
        int r  = (i < 4) ? (ty*4 + i) : (64 + ty*4 + (i-4));
        int gr = m0 + r;
        if (gr >= M) continue;
        float2 p0 = *(float2*)&acc[i][0];
        float2 p1 = *(float2*)&acc[i][1];
        float2 p2 = *(float2*)&acc[i][2];
        float2 p3 = *(float2*)&acc[i][3];
        float vals[8] = {p0.x, p0.y, p1.x, p1.y, p2.x, p2.y, p3.x, p3.y};
        bf16* rowp = EXT + (size_t)gr*KEXT;
#pragma unroll
        for (int grp = 0; grp < 2; ++grp) {
            union { bf16 h[4]; uint2 u; } uh, um;
#pragma unroll
            for (int j = 0; j < 4; ++j)
                split2(vals[grp*4 + j], uh.h[j], um.h[j]);
            int col = grp*64 + tx*4;
            *(uint2*)(rowp + ph0 + col) = uh.u;
            *(uint2*)(rowp + ph1 + col) = uh.u;
            *(uint2*)(rowp + pm0 + col) = um.u;
        }
    }
}

// ============================================================================
// g transpose + 2-way bf16 split: g[B*N,I] -> gt0/gt1 [B][I][N]
// ============================================================================
__global__ void __launch_bounds__(256)
transpose_split(const float* __restrict__ g, bf16* __restrict__ t0, bf16* __restrict__ t1)
{
    __shared__ float tile[32][33];
    const int b = blockIdx.z, n0 = blockIdx.x*32, i0 = blockIdx.y*32;
    const int lane = threadIdx.x & 31, wrow = threadIdx.x >> 5;
#pragma unroll
    for (int rr = 0; rr < 4; ++rr) {
        int n = n0 + wrow + rr*8;
        tile[wrow + rr*8][lane] = g[((size_t)b*NPIX + n)*IDIM + i0 + lane];
    }
    __syncthreads();
#pragma unroll
    for (int rr = 0; rr < 4; ++rr) {
        int i = i0 + wrow + rr*8;
        int n = n0 + lane;
        float a = tile[lane][wrow + rr*8];
        bf16 h = __float2bfloat16(a);
        bf16 l = __float2bfloat16(a - __bfloat162float(h));
        size_t o = ((size_t)b*IDIM + i)*NPIX + n;
        t0[o] = h; t1[o] = l;
    }
}

// ============================================================================
// Row softmax in place; also emits bf16 hi/lo splits of w.
// ============================================================================
__global__ void __launch_bounds__(256)
softmax_rows(float* __restrict__ W, bf16* __restrict__ Whi, bf16* __restrict__ Wlo)
{
    __shared__ float4 buf4[NPIX/4];
    __shared__ float  red[8];
    const size_t row = blockIdx.x;
    float* p = W + row * NPIX;
    bf16* ph = Whi + row * NPIX;
    bf16* pl = Wlo + row * NPIX;
    const int t = threadIdx.x;

    float m = -3.402823466e38f;
    for (int i = t; i < NPIX/4; i += 256) {
        float4 v = *(const float4*)(p + i*4);
        buf4[i] = v;
        m = fmaxf(m, fmaxf(fmaxf(v.x, v.y), fmaxf(v.z, v.w)));
    }
#pragma unroll
    for (int o = 16; o > 0; o >>= 1) m = fmaxf(m, __shfl_xor_sync(0xffffffffu, m, o));
    if ((t & 31) == 0) red[t >> 5] = m;
    __syncthreads();
    float bm = red[0];
#pragma unroll
    for (int wv = 1; wv < 8; ++wv) bm = fmaxf(bm, red[wv]);
    __syncthreads();

    float s = 0.f;
    for (int i = t; i < NPIX/4; i += 256) {
        float4 v = buf4[i];
        v.x = __expf(v.x - bm); v.y = __expf(v.y - bm);
        v.z = __expf(v.z - bm); v.w = __expf(v.w - bm);
        buf4[i] = v;
        s += (v.x + v.y) + (v.z + v.w);
    }
#pragma unroll
    for (int o = 16; o > 0; o >>= 1) s += __shfl_xor_sync(0xffffffffu, s, o);
    if ((t & 31) == 0) red[t >> 5] = s;
    __syncthreads();
    float bs = red[0];
#pragma unroll
    for (int wv = 1; wv < 8; ++wv) bs += red[wv];
    const float inv = 1.0f / bs;

    for (int i = t; i < NPIX/4; i += 256) {
        float4 v = buf4[i];
        v.x *= inv; v.y *= inv; v.z *= inv; v.w *= inv;
        *(float4*)(p + i*4) = v;
        union { bf16 h[4]; uint2 u; } H, L;
        H.h[0] = __float2bfloat16(v.x); L.h[0] = __float2bfloat16(v.x - __bfloat162float(H.h[0]));
        H.h[1] = __float2bfloat16(v.y); L.h[1] = __float2bfloat16(v.y - __bfloat162float(H.h[1]));
        H.h[2] = __float2bfloat16(v.z); L.h[2] = __float2bfloat16(v.z - __bfloat162float(H.h[2]));
        H.h[3] = __float2bfloat16(v.w); L.h[3] = __float2bfloat16(v.w - __bfloat162float(H.h[3]));
        *(uint2*)(ph + i*4) = H.u;
        *(uint2*)(pl + i*4) = L.u;
    }
}

// ============================================================================
extern "C" void kernel_launch(void* const* d_in, const int* in_sizes, int n_in,
                              void* d_out, int out_size)
{
    const float* x   = (const float*)d_in[0];
    const float* wth = (const float*)d_in[1];
    const float* wph = (const float*)d_in[2];
    const float* wgv = (const float*)d_in[3];
    const float* wo  = (const float*)d_in[4];
    float* out0 = (float*)d_out;
    float* W    = out0 + (long long)OUT0;

    float *gv, *ov;
    bf16 *thx, *phx, *gt0, *gt1, *whi, *wlo;
    cudaGetSymbolAddress((void**)&gv,  g_gval);
    cudaGetSymbolAddress((void**)&ov,  g_oval);
    cudaGetSymbolAddress((void**)&thx, g_thx);
    cudaGetSymbolAddress((void**)&phx, g_phx);
    cudaGetSymbolAddress((void**)&gt0, g_gt0);
    cudaGetSymbolAddress((void**)&gt1, g_gt1);
    cudaGetSymbolAddress((void**)&whi, g_whi);
    cudaGetSymbolAddress((void**)&wlo, g_wlo);

    dim3 blk(256);

    // 1) theta+phi projections with ext-split epilogue; g projection fp32
    proj_split<<<dim3(1, 196, 2), blk>>>(x, wth, wph, thx, phx, BATCH*NPIX, CDIM);
    sgemm_nn<<<dim3(1, 196, 1), blk>>>(x, wgv, gv, BATCH*NPIX, IDIM, CDIM, nullptr);

    // 2) g transpose + 2-way split
    transpose_split<<<dim3(98, 4, 8), blk>>>(gv, gt0, gt1);

    // 3) logits = thx @ phx^T  (ext K=384: hh+hm+mh, bf16 HMMA, 2-stage pipe)
    gemm_nt_bf16<<<dim3(25, 25, 8), blk>>>(thx, phx, W, NPIX, NPIX, KEXT,
                                           (long)NPIX*KEXT, (long)NPIX*KEXT,
                                           (long)NPIX*NPIX);

    // 4) softmax rows in place + emit bf16 splits
    softmax_rows<<<BATCH*NPIX, 256>>>(W, whi, wlo);

    // 5) o = w @ g (bf16 HMMA, 3 combos, 2-stage pipe)
    ogemm_mma<<<dim3(25, 8), blk>>>(whi, wlo, gt0, gt1, ov);

    // 6) out = o @ w_o + x
    sgemm_nn<<<dim3(2, 196, 1), blk>>>(ov, wo, out0, BATCH*NPIX, CDIM, IDIM, x);
}

// round 12
// speedup vs baseline: 1.7561x; 1.0609x over previous
#include <cuda_runtime.h>
#include <cuda_bf16.h>
#include <cstdint>

#define BATCH 8
#define NPIX  3136
#define CDIM  256
#define IDIM  128
#define KEXT  384           // 3 combos x 128: theta=[h,h,m], phi=[h,m,h]
#define OUT0  (BATCH*NPIX*CDIM)

typedef __nv_bfloat16 bf16;

// ---------------- scratch (__device__ globals; no allocation allowed) ------
static __device__ __align__(16) float g_gval[BATCH*NPIX*IDIM];
static __device__ __align__(16) float g_oval[BATCH*NPIX*IDIM];
static __device__ __align__(16) bf16  g_thx[(size_t)BATCH*NPIX*KEXT];  // theta ext splits
static __device__ __align__(16) bf16  g_phx[(size_t)BATCH*NPIX*KEXT];  // phi   ext splits
static __device__ __align__(16) bf16  g_gt0[BATCH*IDIM*NPIX];          // g^T hi
static __device__ __align__(16) bf16  g_gt1[BATCH*IDIM*NPIX];          // g^T lo

// ---------------- PTX helpers ----------------------------------------------
__device__ __forceinline__ uint32_t smem_u32(const void* p) {
    uint32_t a;
    asm("{ .reg .u64 t; cvta.to.shared.u64 t, %1; cvt.u32.u64 %0, t; }" : "=r"(a) : "l"(p));
    return a;
}
__device__ __forceinline__ void cp_async16(uint32_t dst, const void* src) {
    unsigned long long gsrc = __cvta_generic_to_global(const_cast<void*>(src));
    asm volatile("cp.async.cg.shared.global [%0], [%1], 16;" :: "r"(dst), "l"(gsrc) : "memory");
}
#define CP_COMMIT()        asm volatile("cp.async.commit_group;" ::: "memory")
#define CP_WAIT1()         asm volatile("cp.async.wait_group 1;" ::: "memory")
#define CP_WAIT0()         asm volatile("cp.async.wait_group 0;" ::: "memory")

__device__ __forceinline__ void ldsm4(uint32_t& r0, uint32_t& r1, uint32_t& r2, uint32_t& r3,
                                      uint32_t addr) {
    asm volatile("ldmatrix.sync.aligned.m8n8.x4.shared.b16 {%0,%1,%2,%3}, [%4];"
                 : "=r"(r0), "=r"(r1), "=r"(r2), "=r"(r3) : "r"(addr));
}
__device__ __forceinline__ void mma_bf16(float* c, const uint32_t* a, const uint32_t* b) {
    asm volatile("mma.sync.aligned.m16n8k16.row.col.f32.bf16.bf16.f32 "
                 "{%0,%1,%2,%3}, {%4,%5,%6,%7}, {%8,%9}, {%0,%1,%2,%3};"
                 : "+f"(c[0]), "+f"(c[1]), "+f"(c[2]), "+f"(c[3])
                 : "r"(a[0]), "r"(a[1]), "r"(a[2]), "r"(a[3]), "r"(b[0]), "r"(b[1]));
}

// swizzle for 128/64/32-byte row tiles
template<int ROWB>
__device__ __forceinline__ uint32_t swz(uint32_t off) {
    const uint32_t mask = (ROWB == 128) ? 0x70u : (ROWB == 64) ? 0x30u : 0x10u;
    return off ^ ((off >> 3) & mask);
}

// 128-row x (ROWB bytes) tile loader via cp.async, row clamp.
template<int ROWB>
__device__ __forceinline__ void load_tile(uint32_t sbase, const char* gsrc,
                                          long rowStride, int maxRow, int tid) {
    const int CPR = ROWB / 16;          // 16B chunks per row
    const int TOT = 128 * CPR;          // total chunks
#pragma unroll
    for (int i = 0; i < TOT/256; ++i) {
        int idx = tid + i*256;
        int r = idx / CPR, cq = idx % CPR;
        int rr = r < maxRow ? r : maxRow - 1;
        const char* src = gsrc + (long)rr*rowStride + cq*16;
        cp_async16(sbase + swz<ROWB>(r*ROWB + cq*16), src);
    }
}

// Per-warp fragment loads (A: 4 m16 tiles, B: 4 n8 tiles) for one k16 step.
template<int ROWB>
__device__ __forceinline__ void lds_afrag(uint32_t abase, int m_w, int ks, int lane,
                                          uint32_t Af[4][4]) {
    int q = lane >> 3;
#pragma unroll
    for (int i = 0; i < 4; ++i) {
        int row = m_w + i*16 + ((q & 1) << 3) + (lane & 7);
        int col = ks*32 + ((q >> 1) << 4);
        ldsm4(Af[i][0], Af[i][1], Af[i][2], Af[i][3], abase + swz<ROWB>(row*ROWB + col));
    }
}
template<int ROWB>
__device__ __forceinline__ void lds_bfrag(uint32_t bbase, int n_w, int ks, int lane,
                                          uint32_t Bf[4][2]) {
    int q = lane >> 3;
#pragma unroll
    for (int jj = 0; jj < 2; ++jj) {
        int row = n_w + jj*16 + ((q >> 1) << 3) + (lane & 7);
        int col = ks*32 + ((q & 1) << 4);
        ldsm4(Bf[jj*2][0], Bf[jj*2][1], Bf[jj*2+1][0], Bf[jj*2+1][1],
              bbase + swz<ROWB>(row*ROWB + col));
    }
}

// ============================================================================
// bf16 NT GEMM via mma.sync: C[M,N] = A[M,K]·B[N,K]^T, K mult of 32.
// Block 128x128, 8 warps, warp tile 64x32.
// 2-stage cp.async double buffer, K-chunk 32 (64B rows), 32KB static smem.
// ============================================================================
__global__ void __launch_bounds__(256)
gemm_nt_bf16(const bf16* __restrict__ A, const bf16* __restrict__ B, float* __restrict__ C,
             int M, int N, int Kext, long sA, long sB, long sC)
{
    __shared__ __align__(128) char smbuf[32768];   // 2 stages x (8KB A + 8KB B)
    const uint32_t sb = smem_u32(smbuf);
    const int tid = threadIdx.x, lane = tid & 31, wid = tid >> 5;
    const int m_w = (wid & 1)*64, n_w = (wid >> 1)*32;
    const int b = blockIdx.z, m0 = blockIdx.y*128, n0 = blockIdx.x*128;
    const char* Ab = (const char*)(A + (size_t)b*sA) + (size_t)m0*Kext*2;
    const char* Bb = (const char*)(B + (size_t)b*sB) + (size_t)n0*Kext*2;
    const long rsA = (long)Kext*2;
    const int  mRem = M - m0, nRem = N - n0;
    const int  nc = Kext >> 5;          // chunks of 32 (12 for KEXT=384)

    float acc[4][4][4];
#pragma unroll
    for (int i = 0; i < 4; ++i)
#pragma unroll
        for (int j = 0; j < 4; ++j)
#pragma unroll
            for (int v = 0; v < 4; ++v) acc[i][j][v] = 0.f;

    // stage s base = sb + s*16384; A at +0 (8KB), B at +8192
    load_tile<64>(sb,        Ab, rsA, mRem, tid);
    load_tile<64>(sb + 8192, Bb, rsA, nRem, tid);
    CP_COMMIT();

    for (int c = 0; c < nc; ++c) {
        if (c + 1 < nc) {
            uint32_t s1 = ((c + 1) & 1) * 16384u;
            load_tile<64>(sb + s1,        Ab + (long)(c+1)*64, rsA, mRem, tid);
            load_tile<64>(sb + s1 + 8192, Bb + (long)(c+1)*64, rsA, nRem, tid);
            CP_COMMIT();
            CP_WAIT1();
        } else {
            CP_WAIT0();
        }
        __syncthreads();
        uint32_t abase = sb + (uint32_t)(c & 1)*16384u;
        uint32_t bbase = abase + 8192;
        uint32_t Af[4][4], Bf[4][2];
#pragma unroll
        for (int ks = 0; ks < 2; ++ks) {
            lds_afrag<64>(abase, m_w, ks, lane, Af);
            lds_bfrag<64>(bbase, n_w, ks, lane, Bf);
#pragma unroll
            for (int i = 0; i < 4; ++i)
#pragma unroll
                for (int j = 0; j < 4; ++j)
                    mma_bf16(acc[i][j], Af[i], Bf[j]);
        }
        __syncthreads();
    }

    float* Cb = C + (size_t)b*sC;
    const int g = lane >> 2, tg = lane & 3;
#pragma unroll
    for (int i = 0; i < 4; ++i) {
        int r0 = m0 + m_w + i*16 + g;
        int r1 = r0 + 8;
#pragma unroll
        for (int j = 0; j < 4; ++j) {
            int col = n0 + n_w + j*8 + tg*2;
            if (col < N) {
                if (r0 < M) *(float2*)(Cb + (size_t)r0*N + col) = make_float2(acc[i][j][0], acc[i][j][1]);
                if (r1 < M) *(float2*)(Cb + (size_t)r1*N + col) = make_float2(acc[i][j][2], acc[i][j][3]);
            }
        }
    }
}

// ============================================================================
// o = w·g via mma.sync, 3 combos/chunk: whi·ghi + whi·glo + wlo·ghi.
// Reads fp32 W directly; splits w -> whi/wlo bf16 in-kernel (regs -> STS).
// Block 128(m) x 128(n=i). W tile single-buffered (reg-prefetched LDG);
// g tiles 2-stage cp.async. K-chunk 16 (32B rows). 24KB static smem.
// grid (25, 8).
// ============================================================================
__global__ void __launch_bounds__(256)
ogemm_mma(const float* __restrict__ W,
          const bf16* __restrict__ Gh,  const bf16* __restrict__ Gl,
          float* __restrict__ Ov)
{
    __shared__ __align__(128) char smbuf[24576];
    // [0,4096): whi tile  [4096,8192): wlo tile (128x16 bf16, 32B rows, swz32)
    // [8192,16384): g stage0 (ghi@+0, glo@+4096)   [16384,24576): g stage1
    const uint32_t sb = smem_u32(smbuf);
    const int tid = threadIdx.x, lane = tid & 31, wid = tid >> 5;
    const int m_w = (wid & 1)*64, n_w = (wid >> 1)*32;
    const int b = blockIdx.y, m0 = blockIdx.x*128;
    const float* Wb = W + (size_t)b*NPIX*NPIX + (size_t)m0*NPIX;
    const char* Bh = (const char*)(Gh + (size_t)b*IDIM*NPIX);
    const char* Bl = (const char*)(Gl + (size_t)b*IDIM*NPIX);
    const long rsG = (long)NPIX*2;
    const int mRem = NPIX - m0;
    const int nc = NPIX / 16;   // 196 chunks of K=16

    float acc[4][4][4];
#pragma unroll
    for (int i = 0; i < 4; ++i)
#pragma unroll
        for (int j = 0; j < 4; ++j)
#pragma unroll
            for (int v = 0; v < 4; ++v) acc[i][j][v] = 0.f;

    // W register-prefetch pattern: 2 threads/row, 8 fp32 each.
    const int wr  = tid >> 1;                       // tile row 0..127
    const int wrc = (wr < mRem) ? wr : (mRem - 1);  // clamped source row
    const int wcb = (tid & 1) * 8;                  // col base within chunk
    const float* wptr = Wb + (size_t)wrc*NPIX + wcb;
    const uint32_t woff0 = swz<32>((uint32_t)wr*32 + (uint32_t)wcb*2);
    const uint32_t woff1 = swz<32>((uint32_t)wr*32 + (uint32_t)wcb*2 + 8);

    float4 wreg0 = *(const float4*)(wptr);
    float4 wreg1 = *(const float4*)(wptr + 4);

    // g chunk 0 -> stage0
    load_tile<32>(sb +  8192, Bh, rsG, 128, tid);
    load_tile<32>(sb + 12288, Bl, rsG, 128, tid);
    CP_COMMIT();

    for (int c = 0; c < nc; ++c) {
        // 1. split + STS current W chunk (post-barrier from previous iter)
        {
            float f[8] = {wreg0.x, wreg0.y, wreg0.z, wreg0.w,
                          wreg1.x, wreg1.y, wreg1.z, wreg1.w};
            union { bf16 h[4]; uint2 u; } H0, H1, L0, L1;
#pragma unroll
            for (int j = 0; j < 4; ++j) {
                bf16 h = __float2bfloat16(f[j]);
                H0.h[j] = h;
                L0.h[j] = __float2bfloat16(f[j] - __bfloat162float(h));
            }
#pragma unroll
            for (int j = 0; j < 4; ++j) {
                bf16 h = __float2bfloat16(f[4+j]);
                H1.h[j] = h;
                L1.h[j] = __float2bfloat16(f[4+j] - __bfloat162float(h));
            }
            *(uint2*)(smbuf + woff0)        = H0.u;
            *(uint2*)(smbuf + woff1)        = H1.u;
            *(uint2*)(smbuf + 4096 + woff0) = L0.u;
            *(uint2*)(smbuf + 4096 + woff1) = L1.u;
        }
        // 2. g pipeline: issue c+1, retire c
        if (c + 1 < nc) {
            uint32_t gs = sb + 8192 + (uint32_t)((c+1) & 1)*8192u;
            const long kb = (long)(c+1)*32;
            load_tile<32>(gs,        Bh + kb, rsG, 128, tid);
            load_tile<32>(gs + 4096, Bl + kb, rsG, 128, tid);
            CP_COMMIT();
            CP_WAIT1();
        } else {
            CP_WAIT0();
        }
        __syncthreads();
        // 3. prefetch W regs for c+1 (latency covered by MMA below)
        if (c + 1 < nc) {
            const float* wp = wptr + (size_t)(c+1)*16;
            wreg0 = *(const float4*)(wp);
            wreg1 = *(const float4*)(wp + 4);
        }
        // 4. MMA on chunk c
        uint32_t gbase = sb + 8192 + (uint32_t)(c & 1)*8192u;
        uint32_t Af[4][4], Bg[4][2], Bl2[4][2];
        lds_afrag<32>(sb,           m_w, 0, lane, Af);     // whi
        lds_bfrag<32>(gbase,        n_w, 0, lane, Bg);     // ghi
        lds_bfrag<32>(gbase + 4096, n_w, 0, lane, Bl2);    // glo
#pragma unroll
        for (int i = 0; i < 4; ++i)
#pragma unroll
            for (int j = 0; j < 4; ++j) {
                mma_bf16(acc[i][j], Af[i], Bg[j]);
                mma_bf16(acc[i][j], Af[i], Bl2[j]);
            }
        lds_afrag<32>(sb + 4096, m_w, 0, lane, Af);        // wlo
#pragma unroll
        for (int i = 0; i < 4; ++i)
#pragma unroll
            for (int j = 0; j < 4; ++j)
                mma_bf16(acc[i][j], Af[i], Bg[j]);
        __syncthreads();   // protect W tiles before next STS
    }

    float* Ob = Ov + (size_t)b*NPIX*IDIM;
    const int g = lane >> 2, tg = lane & 3;
#pragma unroll
    for (int i = 0; i < 4; ++i) {
        int r0 = m0 + m_w + i*16 + g;
        int r1 = r0 + 8;
#pragma unroll
        for (int j = 0; j < 4; ++j) {
            int col = n_w + j*8 + tg*2;
            if (r0 < NPIX) *(float2*)(Ob + (size_t)r0*IDIM + col) = make_float2(acc[i][j][0], acc[i][j][1]);
            if (r1 < NPIX) *(float2*)(Ob + (size_t)r1*IDIM + col) = make_float2(acc[i][j][2], acc[i][j][3]);
        }
    }
}

// ---------------- packed fp32x2 FMA (small fp32 GEMMs) ---------------------
#define FMA2(d,a,b) asm("fma.rn.f32x2 %0, %1, %2, %0;" : "+l"(d) : "l"(a), "l"(b))
#define PACK2(d,x)  asm("mov.b64 %0, {%1, %1};" : "=l"(d) : "f"(x))

__device__ __forceinline__ void mma_tile(const float (*As)[132], const float (*Bs)[132],
                                         int ty, int tx, unsigned long long acc[8][4])
{
#pragma unroll
    for (int k = 0; k < 16; ++k) {
        float4 a0 = *(const float4*)&As[k][ty*4];
        float4 a1 = *(const float4*)&As[k][64 + ty*4];
        unsigned long long b0 = *(const unsigned long long*)&Bs[k][tx*4];
        unsigned long long b1 = *(const unsigned long long*)&Bs[k][tx*4 + 2];
        unsigned long long b2 = *(const unsigned long long*)&Bs[k][64 + tx*4];
        unsigned long long b3 = *(const unsigned long long*)&Bs[k][64 + tx*4 + 2];
        float av[8] = {a0.x,a0.y,a0.z,a0.w,a1.x,a1.y,a1.z,a1.w};
#pragma unroll
        for (int i = 0; i < 8; ++i) {
            unsigned long long ap;
            PACK2(ap, av[i]);
            FMA2(acc[i][0], ap, b0);
            FMA2(acc[i][1], ap, b1);
            FMA2(acc[i][2], ap, b2);
            FMA2(acc[i][3], ap, b3);
        }
    }
}

// ============================================================================
// fp32 NN GEMM (g projection + final epilogue)
// ============================================================================
__global__ void __launch_bounds__(256)
sgemm_nn(const float* __restrict__ A, const float* __restrict__ B, float* __restrict__ C,
         int M, int N, int K, const float* __restrict__ resid)
{
    __shared__ float As[16][132];
    __shared__ float Bs[16][132];
    const int m0 = blockIdx.y * 128;
    const int n0 = blockIdx.x * 128;
    const int t  = threadIdx.x;
    const int tx = t & 15, ty = t >> 4;

    unsigned long long acc[8][4];
#pragma unroll
    for (int i = 0; i < 8; ++i)
#pragma unroll
        for (int j = 0; j < 4; ++j) acc[i][j] = 0ull;

    float4 aReg[2], bReg[2];
    const int nk = K >> 4;

#pragma unroll
    for (int s = 0; s < 2; ++s) {
        int id = t + s*256;
        int r = id >> 2, c4 = id & 3;
        int gr = m0 + r;
        aReg[s] = (gr < M) ? *(const float4*)(A + (long long)gr*K + c4*4)
                           : make_float4(0.f,0.f,0.f,0.f);
        int kr = id >> 5, c = id & 31;
        bReg[s] = *(const float4*)(B + (long long)kr*N + n0 + c*4);
    }

    for (int kc = 0; kc < nk; ++kc) {
#pragma unroll
        for (int s = 0; s < 2; ++s) {
            int id = t + s*256;
            int r = id >> 2, c4 = id & 3;
            As[c4*4+0][r] = aReg[s].x; As[c4*4+1][r] = aReg[s].y;
            As[c4*4+2][r] = aReg[s].z; As[c4*4+3][r] = aReg[s].w;
            int kr = id >> 5, c = id & 31;
            *(float4*)&Bs[kr][c*4] = bReg[s];
        }
        __syncthreads();
        if (kc + 1 < nk) {
            const int k0 = (kc + 1) * 16;
#pragma unroll
            for (int s = 0; s < 2; ++s) {
                int id = t + s*256;
                int r = id >> 2, c4 = id & 3;
                int gr = m0 + r;
                aReg[s] = (gr < M) ? *(const float4*)(A + (long long)gr*K + k0 + c4*4)
                                   : make_float4(0.f,0.f,0.f,0.f);
                int kr = id >> 5, c = id & 31;
                bReg[s] = *(const float4*)(B + (long long)(k0+kr)*N + n0 + c*4);
            }
        }
        mma_tile(As, Bs, ty, tx, acc);
        __syncthreads();
    }

#pragma unroll
    for (int i = 0; i < 8; ++i) {
        int r  = (i < 4) ? (ty*4 + i) : (64 + ty*4 + (i-4));
        int gr = m0 + r;
        if (gr >= M) continue;
        float* Cr = C + (long long)gr*N + n0;
        float2 p0 = *(float2*)&acc[i][0];
        float2 p1 = *(float2*)&acc[i][1];
        float2 p2 = *(float2*)&acc[i][2];
        float2 p3 = *(float2*)&acc[i][3];
        float4 v0 = make_float4(p0.x, p0.y, p1.x, p1.y);
        float4 v1 = make_float4(p2.x, p2.y, p3.x, p3.y);
        if (resid) {
            const float* Rr = resid + (long long)gr*N + n0;
            float4 r0 = *(const float4*)(Rr + tx*4);
            float4 r1 = *(const float4*)(Rr + 64 + tx*4);
            v0.x += r0.x; v0.y += r0.y; v0.z += r0.z; v0.w += r0.w;
            v1.x += r1.x; v1.y += r1.y; v1.z += r1.z; v1.w += r1.w;
        }
        *(float4*)(Cr + tx*4)      = v0;
        *(float4*)(Cr + 64 + tx*4) = v1;
    }
}

// ============================================================================
// Projection + 2-way split -> extended-K bf16 layout (3 blocks of 128).
// blockIdx.z: 0 = theta (ext: h,h,m), 1 = phi (ext: h,m,h).
// ============================================================================
__device__ __forceinline__ void split2(float a, bf16& h, bf16& m) {
    h = __float2bfloat16(a); float r = a - __bfloat162float(h);
    m = __float2bfloat16(r);
}

__global__ void __launch_bounds__(256)
proj_split(const float* __restrict__ A,
           const float* __restrict__ Bth, const float* __restrict__ Bph,
           bf16* __restrict__ THX, bf16* __restrict__ PHX, int M, int K)
{
    const int N = IDIM;
    const float* B = blockIdx.z ? Bph : Bth;
    bf16* EXT = blockIdx.z ? PHX : THX;
    int ph0, ph1, pm0;
    if (blockIdx.z == 0) { ph0 = 0; ph1 = 128; pm0 = 256; }   // theta: h,h,m
    else                 { ph0 = 0; ph1 = 256; pm0 = 128; }   // phi:   h,m,h

    __shared__ float As[16][132];
    __shared__ float Bs[16][132];
    const int m0 = blockIdx.y * 128;
    const int t  = threadIdx.x;
    const int tx = t & 15, ty = t >> 4;

    unsigned long long acc[8][4];
#pragma unroll
    for (int i = 0; i < 8; ++i)
#pragma unroll
        for (int j = 0; j < 4; ++j) acc[i][j] = 0ull;

    float4 aReg[2], bReg[2];
    const int nk = K >> 4;

#pragma unroll
    for (int s = 0; s < 2; ++s) {
        int id = t + s*256;
        int r = id >> 2, c4 = id & 3;
        int gr = m0 + r;
        aReg[s] = (gr < M) ? *(const float4*)(A + (long long)gr*K + c4*4)
                           : make_float4(0.f,0.f,0.f,0.f);
        int kr = id >> 5, c = id & 31;
        bReg[s] = *(const float4*)(B + (long long)kr*N + c*4);
    }

    for (int kc = 0; kc < nk; ++kc) {
#pragma unroll
        for (int s = 0; s < 2; ++s) {
            int id = t + s*256;
            int r = id >> 2, c4 = id & 3;
            As[c4*4+0][r] = aReg[s].x; As[c4*4+1][r] = aReg[s].y;
            As[c4*4+2][r] = aReg[s].z; As[c4*4+3][r] = aReg[s].w;
            int kr = id >> 5, c = id & 31;
            *(float4*)&Bs[kr][c*4] = bReg[s];
        }
        __syncthreads();
        if (kc + 1 < nk) {
            const int k0 = (kc + 1) * 16;
#pragma unroll
            for (int s = 0; s < 2; ++s) {
                int id = t + s*256;
                int r = id >> 2, c4 = id & 3;
                int gr = m0 + r;
                aReg[s] = (gr < M) ? *(const float4*)(A + (long long)gr*K + k0 + c4*4)
                                   : make_float4(0.f,0.f,0.f,0.f);
                int kr = id >> 5, c = id & 31;
                bReg[s] = *(const float4*)(B + (long long)(k0+kr)*N + c*4);
            }
        }
        mma_tile(As, Bs, ty, tx, acc);
        __syncthreads();
    }

#pragma unroll
    for (int i = 0; i < 8; ++i) {
        int r  = (i < 4) ? (ty*4 + i) : (64 + ty*4 + (i-4));
        int gr = m0 + r;
        if (gr >= M) continue;
        float2 p0 = *(float2*)&acc[i][0];
        float2 p1 = *(float2*)&acc[i][1];
        float2 p2 = *(float2*)&acc[i][2];
        float2 p3 = *(float2*)&acc[i][3];
        float vals[8] = {p0.x, p0.y, p1.x, p1.y, p2.x, p2.y, p3.x, p3.y};
        bf16* rowp = EXT + (size_t)gr*KEXT;
#pragma unroll
        for (int grp = 0; grp < 2; ++grp) {
            union { bf16 h[4]; uint2 u; } uh, um;
#pragma unroll
            for (int j = 0; j < 4; ++j)
                split2(vals[grp*4 + j], uh.h[j], um.h[j]);
            int col = grp*64 + tx*4;
            *(uint2*)(rowp + ph0 + col) = uh.u;
            *(uint2*)(rowp + ph1 + col) = uh.u;
            *(uint2*)(rowp + pm0 + col) = um.u;
        }
    }
}

// ============================================================================
// g transpose + 2-way bf16 split: g[B*N,I] -> gt0/gt1 [B][I][N]
// ============================================================================
__global__ void __launch_bounds__(256)
transpose_split(const float* __restrict__ g, bf16* __restrict__ t0, bf16* __restrict__ t1)
{
    __shared__ float tile[32][33];
    const int b = blockIdx.z, n0 = blockIdx.x*32, i0 = blockIdx.y*32;
    const int lane = threadIdx.x & 31, wrow = threadIdx.x >> 5;
#pragma unroll
    for (int rr = 0; rr < 4; ++rr) {
        int n = n0 + wrow + rr*8;
        tile[wrow + rr*8][lane] = g[((size_t)b*NPIX + n)*IDIM + i0 + lane];
    }
    __syncthreads();
#pragma unroll
    for (int rr = 0; rr < 4; ++rr) {
        int i = i0 + wrow + rr*8;
        int n = n0 + lane;
        float a = tile[lane][wrow + rr*8];
        bf16 h = __float2bfloat16(a);
        bf16 l = __float2bfloat16(a - __bfloat162float(h));
        size_t o = ((size_t)b*IDIM + i)*NPIX + n;
        t0[o] = h; t1[o] = l;
    }
}

// ============================================================================
// Row softmax in place (fp32 only; o-GEMM consumes fp32 W and splits itself).
// ============================================================================
__global__ void __launch_bounds__(256)
softmax_rows(float* __restrict__ W)
{
    __shared__ float4 buf4[NPIX/4];
    __shared__ float  red[8];
    float* p = W + (size_t)blockIdx.x * NPIX;
    const int t = threadIdx.x;

    float m = -3.402823466e38f;
    for (int i = t; i < NPIX/4; i += 256) {
        float4 v = *(const float4*)(p + i*4);
        buf4[i] = v;
        m = fmaxf(m, fmaxf(fmaxf(v.x, v.y), fmaxf(v.z, v.w)));
    }
#pragma unroll
    for (int o = 16; o > 0; o >>= 1) m = fmaxf(m, __shfl_xor_sync(0xffffffffu, m, o));
    if ((t & 31) == 0) red[t >> 5] = m;
    __syncthreads();
    float bm = red[0];
#pragma unroll
    for (int wv = 1; wv < 8; ++wv) bm = fmaxf(bm, red[wv]);
    __syncthreads();

    float s = 0.f;
    for (int i = t; i < NPIX/4; i += 256) {
        float4 v = buf4[i];
        v.x = __expf(v.x - bm); v.y = __expf(v.y - bm);
        v.z = __expf(v.z - bm); v.w = __expf(v.w - bm);
        buf4[i] = v;
        s += (v.x + v.y) + (v.z + v.w);
    }
#pragma unroll
    for (int o = 16; o > 0; o >>= 1) s += __shfl_xor_sync(0xffffffffu, s, o);
    if ((t & 31) == 0) red[t >> 5] = s;
    __syncthreads();
    float bs = red[0];
#pragma unroll
    for (int wv = 1; wv < 8; ++wv) bs += red[wv];
    const float inv = 1.0f / bs;

    for (int i = t; i < NPIX/4; i += 256) {
        float4 v = buf4[i];
        v.x *= inv; v.y *= inv; v.z *= inv; v.w *= inv;
        *(float4*)(p + i*4) = v;
    }
}

// ============================================================================
extern "C" void kernel_launch(void* const* d_in, const int* in_sizes, int n_in,
                              void* d_out, int out_size)
{
    const float* x   = (const float*)d_in[0];
    const float* wth = (const float*)d_in[1];
    const float* wph = (const float*)d_in[2];
    const float* wgv = (const float*)d_in[3];
    const float* wo  = (const float*)d_in[4];
    float* out0 = (float*)d_out;
    float* W    = out0 + (long long)OUT0;

    float *gv, *ov;
    bf16 *thx, *phx, *gt0, *gt1;
    cudaGetSymbolAddress((void**)&gv,  g_gval);
    cudaGetSymbolAddress((void**)&ov,  g_oval);
    cudaGetSymbolAddress((void**)&thx, g_thx);
    cudaGetSymbolAddress((void**)&phx, g_phx);
    cudaGetSymbolAddress((void**)&gt0, g_gt0);
    cudaGetSymbolAddress((void**)&gt1, g_gt1);

    dim3 blk(256);

    // 1) theta+phi projections with ext-split epilogue; g projection fp32
    proj_split<<<dim3(1, 196, 2), blk>>>(x, wth, wph, thx, phx, BATCH*NPIX, CDIM);
    sgemm_nn<<<dim3(1, 196, 1), blk>>>(x, wgv, gv, BATCH*NPIX, IDIM, CDIM, nullptr);

    // 2) g transpose + 2-way split
    transpose_split<<<dim3(98, 4, 8), blk>>>(gv, gt0, gt1);

    // 3) logits = thx @ phx^T  (ext K=384: hh+hm+mh, bf16 HMMA, 2-stage pipe)
    gemm_nt_bf16<<<dim3(25, 25, 8), blk>>>(thx, phx, W, NPIX, NPIX, KEXT,
                                           (long)NPIX*KEXT, (long)NPIX*KEXT,
                                           (long)NPIX*NPIX);

    // 4) softmax rows in place (fp32 only)
    softmax_rows<<<BATCH*NPIX, 256>>>(W);

    // 5) o = w @ g (fp32 W in, in-kernel split, bf16 HMMA 3 combos, 2-stage g pipe)
    ogemm_mma<<<dim3(25, 8), blk>>>(W, gt0, gt1, ov);

    // 6) out = o @ w_o + x
    sgemm_nn<<<dim3(2, 196, 1), blk>>>(ov, wo, out0, BATCH*NPIX, CDIM, IDIM, x);
}